// round 10
// baseline (speedup 1.0000x reference)
#include <cuda_runtime.h>
#include <cstdint>

#define Bb 2
#define Ss 2048
#define Dd 2048
#define Hh 16
#define HD 128
#define Mtot (Bb*Ss)

// Paired-tf32 global scratch (R3 layout, verified through R7).
// XP/AP: [Mtot][2048] floats:   addr = m*2048 + (k>>3)*8 + (k&3)*2 + ((k>>2)&1)
// WP:    [K/8][N][8 floats]:    addr = (k>>3)*16384 + n*8 + (k&3)*2 + ((k>>2)&1)
// QP/KP: per bh [Ss][128]:      addr = (bh*Ss+s)*128 + (d>>3)*8 + (d&3)*2 + ((d>>2)&1)
// VP:    per bh [128 d][2048]:  addr = (bh*128+d)*2048 + (s>>3)*8 + (s&3)*2 + ((s>>2)&1)
__device__ float g_XP[(size_t)Mtot * Dd];
__device__ float g_WPq[(size_t)Dd * Dd];
__device__ float g_WPk[(size_t)Dd * Dd];
__device__ float g_WPv[(size_t)Dd * Dd];
__device__ float g_WPd[(size_t)Dd * Dd];
__device__ float g_QP[(size_t)Mtot * Dd];
__device__ float g_KP[(size_t)Mtot * Dd];
__device__ float g_VP[(size_t)Mtot * Dd];
__device__ float g_AP[(size_t)Mtot * Dd];

__device__ __forceinline__ float to_tf32(float x) {
    float r;
    asm("cvt.rna.tf32.f32 %0, %1;" : "=f"(r) : "f"(x));
    return r;
}
__device__ __forceinline__ uint32_t u32(float x) { return __float_as_uint(x); }

__device__ __forceinline__ void mma8(float* c, const uint32_t* a, const uint32_t* b) {
    asm volatile(
        "mma.sync.aligned.m16n8k8.row.col.f32.tf32.tf32.f32 "
        "{%0,%1,%2,%3}, {%4,%5,%6,%7}, {%8,%9}, {%0,%1,%2,%3};"
        : "+f"(c[0]), "+f"(c[1]), "+f"(c[2]), "+f"(c[3])
        : "r"(a[0]), "r"(a[1]), "r"(a[2]), "r"(a[3]), "r"(b[0]), "r"(b[1]));
}
__device__ __forceinline__ void cpa16(void* dst, const void* src) {
    uint32_t d = (uint32_t)__cvta_generic_to_shared(dst);
    asm volatile("cp.async.cg.shared.global [%0], [%1], 16;" :: "r"(d), "l"(src));
}
#define CP_COMMIT asm volatile("cp.async.commit_group;")
#define CP_WAIT2  asm volatile("cp.async.wait_group 2;")
#define CP_WAIT1  asm volatile("cp.async.wait_group 1;")
#define CP_WAIT0  asm volatile("cp.async.wait_group 0;")

// ---------------------------------------------------------------------------
// Fast prep kernels (R6/R7, verified).
// ---------------------------------------------------------------------------
__global__ void xprep(const float* __restrict__ X, float* __restrict__ XP) {
    __shared__ float s[2048 + 256];            // addr(g) = g + (g>>3)
    const int m = blockIdx.x;
    const int tid = threadIdx.x;
    const float* src = X + (size_t)m * 2048;
#pragma unroll
    for (int i = 0; i < 2; i++) {
        int f = i * 256 + tid;
        float4 v = *(const float4*)(src + f * 4);
        float* d = s + f * 4 + (f >> 1);       // scalar STS (padded addr not 16B-aligned)
        d[0] = v.x; d[1] = v.y; d[2] = v.z; d[3] = v.w;
    }
    __syncthreads();
    const float* b = s + tid * 9;
    float4 o0 = make_float4(to_tf32(b[0]), to_tf32(b[4]), to_tf32(b[1]), to_tf32(b[5]));
    float4 o1 = make_float4(to_tf32(b[2]), to_tf32(b[6]), to_tf32(b[3]), to_tf32(b[7]));
    float* dst = XP + (size_t)m * 2048 + tid * 8;
    *(float4*)(dst) = o0;
    *(float4*)(dst + 4) = o1;
}

__global__ void wprep4(const float* __restrict__ W0, const float* __restrict__ W1,
                       const float* __restrict__ W2, const float* __restrict__ W3,
                       float* __restrict__ P0, float* __restrict__ P1,
                       float* __restrict__ P2, float* __restrict__ P3) {
    __shared__ float s[8 * 260];
    const int n0 = blockIdx.x * 256;
    const int kb = blockIdx.y;
    const int z  = blockIdx.z;
    const int tid = threadIdx.x;
    const float* W = (z == 0) ? W0 : (z == 1) ? W1 : (z == 2) ? W2 : W3;
    float* WP      = (z == 0) ? P0 : (z == 1) ? P1 : (z == 2) ? P2 : P3;
#pragma unroll
    for (int i = 0; i < 2; i++) {
        int f = i * 256 + tid;
        int r = f >> 6, c4 = (f & 63) * 4;
        float4 v = *(const float4*)(W + (size_t)(kb * 8 + r) * 2048 + n0 + c4);
        *(float4*)(s + r * 260 + c4) = v;
    }
    __syncthreads();
    const int n = tid;
    float4 o0 = make_float4(to_tf32(s[0 * 260 + n]), to_tf32(s[4 * 260 + n]),
                            to_tf32(s[1 * 260 + n]), to_tf32(s[5 * 260 + n]));
    float4 o1 = make_float4(to_tf32(s[2 * 260 + n]), to_tf32(s[6 * 260 + n]),
                            to_tf32(s[3 * 260 + n]), to_tf32(s[7 * 260 + n]));
    float* dst = WP + (size_t)kb * 16384 + (size_t)(n0 + n) * 8;
    *(float4*)(dst) = o0;
    *(float4*)(dst + 4) = o1;
}

// ---------------------------------------------------------------------------
// Pipelined tf32 GEMM, 4-stage cp.async ring, BK=16, one sync per stage.
// BM=BN=128, 256 thr = 8 warps (4m x 2n), warp 32x64.
// As: [128 m][10 float2] (8 data + 2 pad; 20-word stride -> CF phases)
// Bs: [2 kb][128 n][4 float2]
// grid.z selects weight/bias/output set. mode = modebase ? 1+z : 0.
// modes: 0=plain C fp32; 1=Q->QP (qscale folded); 2=K->k_out+KP; 3=V->v_out+VP
// ---------------------------------------------------------------------------
#define ABUF2 (128*10)
#define BBUF2 (2*128*4)
#define GBUF2 (ABUF2 + BBUF2)
#define NSTG 4

__global__ __launch_bounds__(256, 2)
void gemm_tc(const float* __restrict__ Ap,
             const float* __restrict__ Wa, const float* __restrict__ Wb,
             const float* __restrict__ Wc,
             const float* __restrict__ ba, const float* __restrict__ bb,
             const float* __restrict__ bc,
             float* __restrict__ ra, float* __restrict__ rb, float* __restrict__ rc,
             float* __restrict__ pa, float* __restrict__ pb, float* __restrict__ pc,
             int modebase)
{
    extern __shared__ float2 sm2[];

    const int z = blockIdx.z;
    const float* WP   = (z == 0) ? Wa : (z == 1) ? Wb : Wc;
    const float* bias = (z == 0) ? ba : (z == 1) ? bb : bc;
    float* Craw  = (z == 0) ? ra : (z == 1) ? rb : rc;
    float* Cpair = (z == 0) ? pa : (z == 1) ? pb : pc;
    const int mode = modebase ? (1 + z) : 0;

    const int tid  = threadIdx.x;
    const int lane = tid & 31;
    const int wid  = tid >> 5;
    const int mb   = (wid >> 1) * 32;
    const int nb   = (wid & 1) * 64;
    const int lr   = lane >> 2;
    const int lc   = lane & 3;
    const int bx   = blockIdx.x;
    const int by   = blockIdx.y;

    float acc[2][8][4];
#pragma unroll
    for (int f = 0; f < 2; f++)
#pragma unroll
        for (int g = 0; g < 8; g++)
#pragma unroll
            for (int t = 0; t < 4; t++) acc[f][g][t] = 0.f;

    // load BK16 stage kt into ring slot s
    auto issue = [&](int kt, int s) {
        float2* As = sm2 + s * GBUF2;
        float2* Bs = As + ABUF2;
#pragma unroll
        for (int j = 0; j < 2; j++) {
            int idx = j * 256 + tid;           // 512 float4: A 128 x 16 floats
            int m   = idx >> 2;
            int ch  = idx & 3;
            cpa16(As + m * 10 + ch * 2,
                  Ap + (size_t)(by * 128 + m) * 2048 + kt * 16 + ch * 4);
        }
#pragma unroll
        for (int j = 0; j < 2; j++) {
            int idx = j * 256 + tid;           // 512 float4: B 2 kb x 128 n x 8 floats
            int kb  = idx >> 8;
            int r   = idx & 255;
            int n   = r >> 1;
            int ch  = r & 1;
            cpa16(Bs + kb * 512 + n * 4 + ch * 2,
                  WP + (size_t)(kt * 2 + kb) * 16384 + (size_t)(bx * 128 + n) * 8 + ch * 4);
        }
    };

    issue(0, 0); CP_COMMIT;
    issue(1, 1); CP_COMMIT;
    issue(2, 2); CP_COMMIT;

    for (int kt = 0; kt < 128; kt++) {
        if (kt < 126)      { CP_WAIT2; }
        else if (kt == 126){ CP_WAIT1; }
        else               { CP_WAIT0; }
        __syncthreads();
        if (kt + 3 < 128) { issue(kt + 3, (kt + 3) & 3); CP_COMMIT; }

        const float2* As = sm2 + (kt & 3) * GBUF2;
        const float2* Bs = As + ABUF2;

#pragma unroll
        for (int ks = 0; ks < 2; ks++) {
            const float2* ap = As + (mb + lr) * 10 + ks * 4 + lc;
            float2 x00 = ap[0], x01 = ap[80], x10 = ap[160], x11 = ap[240];
            uint32_t a0[4] = {u32(x00.x), u32(x01.x), u32(x00.y), u32(x01.y)};
            uint32_t a1[4] = {u32(x10.x), u32(x11.x), u32(x10.y), u32(x11.y)};
            const float2* bp = Bs + ks * 512 + (nb + lr) * 4 + lc;
#pragma unroll
            for (int g = 0; g < 8; g++) {
                float2 bv = bp[g * 32];
                uint32_t b[2] = {u32(bv.x), u32(bv.y)};
                mma8(acc[0][g], a0, b);
                mma8(acc[1][g], a1, b);
            }
        }
    }

    const float qscale = 0.08838834764831845f;   // folded into Q when mode==1
#pragma unroll
    for (int f = 0; f < 2; f++) {
#pragma unroll
        for (int g = 0; g < 8; g++) {
#pragma unroll
            for (int ii = 0; ii < 2; ii++) {
                int row = by * 128 + mb + f * 16 + lr + 8 * ii;
#pragma unroll
                for (int jj = 0; jj < 2; jj++) {
                    int col = bx * 128 + nb + g * 8 + lc * 2 + jj;
                    float v = acc[f][g][ii * 2 + jj] + bias[col];
                    if (mode == 0) {
                        Craw[(size_t)row * Dd + col] = v;
                    } else {
                        int b_ = row >> 11, s_ = row & 2047;
                        int h_ = col >> 7,  d_ = col & 127;
                        size_t bh = (size_t)(b_ * Hh + h_);
                        if (mode >= 2) Craw[(bh * Ss + s_) * HD + d_] = v;
                        if (mode == 3) {
                            Cpair[(bh * 128 + d_) * 2048 +
                                  (s_ >> 3) * 8 + (s_ & 3) * 2 + ((s_ >> 2) & 1)] = to_tf32(v);
                        } else {
                            float tv = (mode == 1) ? to_tf32(v * qscale) : to_tf32(v);
                            Cpair[(bh * Ss + s_) * 128 +
                                  (d_ >> 3) * 8 + (d_ & 3) * 2 + ((d_ >> 2) & 1)] = tv;
                        }
                    }
                }
            }
        }
    }
}

// ---------------------------------------------------------------------------
// Single-pass tf32 flash attention (R7, verified at 1267.9).
// ---------------------------------------------------------------------------
#define QS2 68
#define KS2 68
#define VS2 36
#define SQ2 (128*QS2)
#define SK2 (64*KS2)
#define SV2 (128*VS2)

__global__ __launch_bounds__(256)
void attn_tc(const float* __restrict__ QP, const float* __restrict__ KP,
             const float* __restrict__ VP, float* __restrict__ AP)
{
    extern __shared__ float2 sm2[];
    float2* sQ = sm2;
    float2* sK = sQ + SQ2;
    float2* sV = sK + 2 * SK2;

    const int qt  = (gridDim.x - 1) - blockIdx.x;
    const int bh  = blockIdx.y;
    const int tid = threadIdx.x;
    const int lane = tid & 31;
    const int wid  = tid >> 5;
    const int lr   = lane >> 2;
    const int lc   = lane & 3;
    const int m_off = wid * 16;

    const float* Qg = QP + ((size_t)bh * Ss + (size_t)qt * 128) * 128;
    const float* Kg = KP + (size_t)bh * Ss * 128;
    const float* Vg = VP + (size_t)bh * 128 * 2048;

#pragma unroll
    for (int i = 0; i < 16; i++) {
        int idx = i * 256 + tid;
        int row = idx >> 5;
        int ch  = idx & 31;
        cpa16(sQ + row * QS2 + ch * 2, Qg + (size_t)row * 128 + ch * 4);
    }
    CP_COMMIT;
#pragma unroll
    for (int i = 0; i < 8; i++) {
        int idx = i * 256 + tid;
        int row = idx >> 5;
        int ch  = idx & 31;
        cpa16(sK + row * KS2 + ch * 2, Kg + (size_t)row * 128 + ch * 4);
    }
#pragma unroll
    for (int i = 0; i < 8; i++) {
        int idx = i * 256 + tid;
        int d   = idx >> 4;
        int ch  = idx & 15;
        cpa16(sV + d * VS2 + ch * 2, Vg + (size_t)d * 2048 + ch * 4);
    }
    CP_COMMIT;

    CP_WAIT1;
    __syncthreads();
    uint32_t qf[16][4];
#pragma unroll
    for (int ks = 0; ks < 16; ks++) {
        const float2* qp = sQ + (m_off + lr) * QS2 + ks * 4 + lc;
        float2 q0 = qp[0], q1 = qp[8 * QS2];
        qf[ks][0] = u32(q0.x); qf[ks][1] = u32(q1.x);
        qf[ks][2] = u32(q0.y); qf[ks][3] = u32(q1.y);
    }

    float o[16][4];
#pragma unroll
    for (int n = 0; n < 16; n++)
#pragma unroll
        for (int j = 0; j < 4; j++) o[n][j] = 0.f;
    float m0 = -1e30f, m1 = -1e30f, l0 = 0.f, l1 = 0.f;

    const int tmax = 2 * qt + 1;
    const int warp_max_row = qt * 128 + m_off + 15;

    for (int t = 0; t <= tmax; t++) {
        const int buf = t & 1;
        if (t < tmax) {
            const int nb2 = (t + 1) & 1;
            float2* dK = sK + nb2 * SK2;
            float2* dV = sV + nb2 * SV2;
            const float* gK = Kg + (size_t)(t + 1) * 64 * 128;
            const float* gV = Vg + (size_t)(t + 1) * 64;
#pragma unroll
            for (int i = 0; i < 8; i++) {
                int idx = i * 256 + tid;
                int row = idx >> 5;
                int ch  = idx & 31;
                cpa16(dK + row * KS2 + ch * 2, gK + (size_t)row * 128 + ch * 4);
            }
#pragma unroll
            for (int i = 0; i < 8; i++) {
                int idx = i * 256 + tid;
                int d   = idx >> 4;
                int ch  = idx & 15;
                cpa16(dV + d * VS2 + ch * 2, gV + (size_t)d * 2048 + ch * 4);
            }
            CP_COMMIT;
            CP_WAIT1;
        } else {
            CP_WAIT0;
        }
        __syncthreads();

        if (t * 64 <= warp_max_row) {
            const float2* sKb = sK + buf * SK2;
            const float2* sVb = sV + buf * SV2;

            float c[8][4];
#pragma unroll
            for (int n = 0; n < 8; n++)
#pragma unroll
                for (int j = 0; j < 4; j++) c[n][j] = 0.f;

#pragma unroll
            for (int ks = 0; ks < 16; ks++) {
                const float2* kp = sKb + lr * KS2 + ks * 4 + lc;
#pragma unroll
                for (int nf = 0; nf < 8; nf++) {
                    float2 bv = kp[nf * 8 * KS2];
                    uint32_t b[2] = {u32(bv.x), u32(bv.y)};
                    mma8(c[nf], qf[ks], b);
                }
            }

            if (t * 64 + 63 > qt * 128 + m_off) {
#pragma unroll
                for (int nf = 0; nf < 8; nf++) {
#pragma unroll
                    for (int j = 0; j < 4; j++) {
                        int col = t * 64 + nf * 8 + 2 * lc + (j & 1);
                        int row = qt * 128 + m_off + lr + 8 * (j >> 1);
                        if (col > row) c[nf][j] = -1e30f;
                    }
                }
            }

            float mt0 = -1e30f, mt1 = -1e30f;
#pragma unroll
            for (int nf = 0; nf < 8; nf++) {
                mt0 = fmaxf(mt0, fmaxf(c[nf][0], c[nf][1]));
                mt1 = fmaxf(mt1, fmaxf(c[nf][2], c[nf][3]));
            }
#pragma unroll
            for (int d = 1; d <= 2; d <<= 1) {
                mt0 = fmaxf(mt0, __shfl_xor_sync(0xffffffffu, mt0, d));
                mt1 = fmaxf(mt1, __shfl_xor_sync(0xffffffffu, mt1, d));
            }
            float nm0 = fmaxf(m0, mt0), nm1 = fmaxf(m1, mt1);
            float corr0 = __expf(m0 - nm0), corr1 = __expf(m1 - nm1);
            m0 = nm0; m1 = nm1;

            float s0 = 0.f, s1 = 0.f;
#pragma unroll
            for (int nf = 0; nf < 8; nf++) {
                c[nf][0] = __expf(c[nf][0] - nm0); s0 += c[nf][0];
                c[nf][1] = __expf(c[nf][1] - nm0); s0 += c[nf][1];
                c[nf][2] = __expf(c[nf][2] - nm1); s1 += c[nf][2];
                c[nf][3] = __expf(c[nf][3] - nm1); s1 += c[nf][3];
            }
#pragma unroll
            for (int d = 1; d <= 2; d <<= 1) {
                s0 += __shfl_xor_sync(0xffffffffu, s0, d);
                s1 += __shfl_xor_sync(0xffffffffu, s1, d);
            }
            l0 = l0 * corr0 + s0;
            l1 = l1 * corr1 + s1;

            if (__any_sync(0xffffffffu, (corr0 != 1.f) || (corr1 != 1.f))) {
#pragma unroll
                for (int n = 0; n < 16; n++) {
                    o[n][0] *= corr0; o[n][1] *= corr0;
                    o[n][2] *= corr1; o[n][3] *= corr1;
                }
            }

#pragma unroll
            for (int ks = 0; ks < 8; ks++) {
                const int src0 = 4 * lr + (lc >> 1);
                const int src1 = src0 + 2;
                float v00 = __shfl_sync(0xffffffffu, c[ks][0], src0);
                float v01 = __shfl_sync(0xffffffffu, c[ks][1], src0);
                float v20 = __shfl_sync(0xffffffffu, c[ks][2], src0);
                float v21 = __shfl_sync(0xffffffffu, c[ks][3], src0);
                float w00 = __shfl_sync(0xffffffffu, c[ks][0], src1);
                float w01 = __shfl_sync(0xffffffffu, c[ks][1], src1);
                float w20 = __shfl_sync(0xffffffffu, c[ks][2], src1);
                float w21 = __shfl_sync(0xffffffffu, c[ks][3], src1);
                float a0f = (lc & 1) ? v01 : v00;
                float a1f = (lc & 1) ? v21 : v20;
                float a2f = (lc & 1) ? w01 : w00;
                float a3f = (lc & 1) ? w21 : w20;
                uint32_t a[4] = {u32(to_tf32(a0f)), u32(to_tf32(a1f)),
                                 u32(to_tf32(a2f)), u32(to_tf32(a3f))};
                const float2* vp = sVb + lr * VS2 + ks * 4 + lc;
#pragma unroll
                for (int nf = 0; nf < 16; nf++) {
                    float2 bv = vp[nf * 8 * VS2];
                    uint32_t b[2] = {u32(bv.x), u32(bv.y)};
                    mma8(o[nf], a, b);
                }
            }
        }
        __syncthreads();
    }

    // epilogue: normalize, convert, write pre-paired AP
    const float inv0 = 1.0f / l0;
    const float inv1 = 1.0f / l1;
    const int b = bh / Hh;
    const int h = bh % Hh;
    const size_t mrow0 = (size_t)b * 2048 + qt * 128 + m_off + lr;
    const size_t mrow1 = mrow0 + 8;
#pragma unroll
    for (int nf = 0; nf < 16; nf++) {
#pragma unroll
        for (int jj = 0; jj < 2; jj++) {
            int dl = 2 * lc + jj;
            size_t cslot = (size_t)(h * 16 + nf) * 8 + (dl & 3) * 2 + (dl >> 2);
            AP[mrow0 * 2048 + cslot] = to_tf32(o[nf][jj] * inv0);
            AP[mrow1 * 2048 + cslot] = to_tf32(o[nf][2 + jj] * inv1);
        }
    }
}

// ---------------------------------------------------------------------------

extern "C" void kernel_launch(void* const* d_in, const int* in_sizes, int n_in,
                              void* d_out, int out_size)
{
    const float* x  = (const float*)d_in[0];
    const float* Wq = (const float*)d_in[1];
    const float* bq = (const float*)d_in[2];
    const float* Wk = (const float*)d_in[3];
    const float* bk = (const float*)d_in[4];
    const float* Wv = (const float*)d_in[5];
    const float* bv = (const float*)d_in[6];
    const float* Wd = (const float*)d_in[7];
    const float* bd = (const float*)d_in[8];

    float* out = (float*)d_out;
    float* a_out = out;
    float* k_out = out + (size_t)Bb * Ss * Dd;
    float* v_out = k_out + (size_t)Bb * Ss * Dd;

    float *xp, *wpq, *wpk, *wpv, *wpd, *qp, *kp, *vp, *ap;
    cudaGetSymbolAddress((void**)&xp,  g_XP);
    cudaGetSymbolAddress((void**)&wpq, g_WPq);
    cudaGetSymbolAddress((void**)&wpk, g_WPk);
    cudaGetSymbolAddress((void**)&wpv, g_WPv);
    cudaGetSymbolAddress((void**)&wpd, g_WPd);
    cudaGetSymbolAddress((void**)&qp,  g_QP);
    cudaGetSymbolAddress((void**)&kp,  g_KP);
    cudaGetSymbolAddress((void**)&vp,  g_VP);
    cudaGetSymbolAddress((void**)&ap,  g_AP);

    xprep<<<Mtot, 256>>>(x, xp);
    wprep4<<<dim3(8, 256, 4), 256>>>(Wq, Wk, Wv, Wd, wpq, wpk, wpv, wpd);

    size_t gsm = (size_t)NSTG * GBUF2 * sizeof(float2);
    cudaFuncSetAttribute(gemm_tc, cudaFuncAttributeMaxDynamicSharedMemorySize, (int)gsm);

    // fused QKV: grid.z selects (Wq,Wk,Wv); modes 1,2,3
    gemm_tc<<<dim3(Dd / 128, Mtot / 128, 3), 256, gsm>>>(
        xp, wpq, wpk, wpv, bq, bk, bv,
        nullptr, k_out, v_out, qp, kp, vp, 1);

    size_t asm_ = (size_t)(SQ2 + 2 * SK2 + 2 * SV2) * sizeof(float2);
    cudaFuncSetAttribute(attn_tc, cudaFuncAttributeMaxDynamicSharedMemorySize, (int)asm_);
    attn_tc<<<dim3(Ss / 128, Bb * Hh), 256, asm_>>>(qp, kp, vp, ap);

    // final projection: mode 0
    gemm_tc<<<dim3(Dd / 128, Mtot / 128, 1), 256, gsm>>>(
        ap, wpd, wpd, wpd, bd, bd, bd,
        a_out, a_out, a_out, nullptr, nullptr, nullptr, 0);
}

// round 11
// speedup vs baseline: 1.1364x; 1.1364x over previous
#include <cuda_runtime.h>
#include <cstdint>

#define Bb 2
#define Ss 2048
#define Dd 2048
#define Hh 16
#define HD 128
#define Mtot (Bb*Ss)

// Paired-tf32 global scratch (R3 layout, verified through R7).
// XP/AP: [Mtot][2048] floats:   addr = m*2048 + (k>>3)*8 + (k&3)*2 + ((k>>2)&1)
// WP:    [K/8][N][8 floats]:    addr = (k>>3)*16384 + n*8 + (k&3)*2 + ((k>>2)&1)
// QP/KP: per bh [Ss][128]:      addr = (bh*Ss+s)*128 + (d>>3)*8 + (d&3)*2 + ((d>>2)&1)
// VP:    per bh [128 d][2048]:  addr = (bh*128+d)*2048 + (s>>3)*8 + (s&3)*2 + ((s>>2)&1)
__device__ float g_XP[(size_t)Mtot * Dd];
__device__ float g_WPq[(size_t)Dd * Dd];
__device__ float g_WPk[(size_t)Dd * Dd];
__device__ float g_WPv[(size_t)Dd * Dd];
__device__ float g_WPd[(size_t)Dd * Dd];
__device__ float g_QP[(size_t)Mtot * Dd];
__device__ float g_KP[(size_t)Mtot * Dd];
__device__ float g_VP[(size_t)Mtot * Dd];
__device__ float g_AP[(size_t)Mtot * Dd];

__device__ __forceinline__ float to_tf32(float x) {
    float r;
    asm("cvt.rna.tf32.f32 %0, %1;" : "=f"(r) : "f"(x));
    return r;
}
__device__ __forceinline__ uint32_t u32(float x) { return __float_as_uint(x); }

__device__ __forceinline__ void mma8(float* c, const uint32_t* a, const uint32_t* b) {
    asm volatile(
        "mma.sync.aligned.m16n8k8.row.col.f32.tf32.tf32.f32 "
        "{%0,%1,%2,%3}, {%4,%5,%6,%7}, {%8,%9}, {%0,%1,%2,%3};"
        : "+f"(c[0]), "+f"(c[1]), "+f"(c[2]), "+f"(c[3])
        : "r"(a[0]), "r"(a[1]), "r"(a[2]), "r"(a[3]), "r"(b[0]), "r"(b[1]));
}
__device__ __forceinline__ void cpa16(void* dst, const void* src) {
    uint32_t d = (uint32_t)__cvta_generic_to_shared(dst);
    asm volatile("cp.async.cg.shared.global [%0], [%1], 16;" :: "r"(d), "l"(src));
}
#define CP_COMMIT asm volatile("cp.async.commit_group;")
#define CP_WAIT1  asm volatile("cp.async.wait_group 1;")
#define CP_WAIT0  asm volatile("cp.async.wait_group 0;")

// ---------------------------------------------------------------------------
// Fast prep kernels (R6/R7, verified).
// ---------------------------------------------------------------------------
__global__ void xprep(const float* __restrict__ X, float* __restrict__ XP) {
    __shared__ float s[2048 + 256];            // addr(g) = g + (g>>3)
    const int m = blockIdx.x;
    const int tid = threadIdx.x;
    const float* src = X + (size_t)m * 2048;
#pragma unroll
    for (int i = 0; i < 2; i++) {
        int f = i * 256 + tid;
        float4 v = *(const float4*)(src + f * 4);
        float* d = s + f * 4 + (f >> 1);       // scalar STS (padded addr not 16B-aligned)
        d[0] = v.x; d[1] = v.y; d[2] = v.z; d[3] = v.w;
    }
    __syncthreads();
    const float* b = s + tid * 9;
    float4 o0 = make_float4(to_tf32(b[0]), to_tf32(b[4]), to_tf32(b[1]), to_tf32(b[5]));
    float4 o1 = make_float4(to_tf32(b[2]), to_tf32(b[6]), to_tf32(b[3]), to_tf32(b[7]));
    float* dst = XP + (size_t)m * 2048 + tid * 8;
    *(float4*)(dst) = o0;
    *(float4*)(dst + 4) = o1;
}

__global__ void wprep4(const float* __restrict__ W0, const float* __restrict__ W1,
                       const float* __restrict__ W2, const float* __restrict__ W3,
                       float* __restrict__ P0, float* __restrict__ P1,
                       float* __restrict__ P2, float* __restrict__ P3) {
    __shared__ float s[8 * 260];
    const int n0 = blockIdx.x * 256;
    const int kb = blockIdx.y;
    const int z  = blockIdx.z;
    const int tid = threadIdx.x;
    const float* W = (z == 0) ? W0 : (z == 1) ? W1 : (z == 2) ? W2 : W3;
    float* WP      = (z == 0) ? P0 : (z == 1) ? P1 : (z == 2) ? P2 : P3;
#pragma unroll
    for (int i = 0; i < 2; i++) {
        int f = i * 256 + tid;
        int r = f >> 6, c4 = (f & 63) * 4;
        float4 v = *(const float4*)(W + (size_t)(kb * 8 + r) * 2048 + n0 + c4);
        *(float4*)(s + r * 260 + c4) = v;
    }
    __syncthreads();
    const int n = tid;
    float4 o0 = make_float4(to_tf32(s[0 * 260 + n]), to_tf32(s[4 * 260 + n]),
                            to_tf32(s[1 * 260 + n]), to_tf32(s[5 * 260 + n]));
    float4 o1 = make_float4(to_tf32(s[2 * 260 + n]), to_tf32(s[6 * 260 + n]),
                            to_tf32(s[3 * 260 + n]), to_tf32(s[7 * 260 + n]));
    float* dst = WP + (size_t)kb * 16384 + (size_t)(n0 + n) * 8;
    *(float4*)(dst) = o0;
    *(float4*)(dst + 4) = o1;
}

// ---------------------------------------------------------------------------
// Pipelined tf32 GEMM (R7-verified BK32 2-stage schedule), with grid.z
// selecting the weight/bias/output set (QKV fusion). Inner loop unchanged.
// BM=BN=128, BK=32, 256 thr = 8 warps (4m x 2n), warp 32x64.
// As: [128 m][20 float2], Bs: [4 kb][128 n][4 float2]
// modes: 0=plain C fp32; 1=Q->QP (qscale folded); 2=K->k_out+KP; 3=V->v_out+VP
// ---------------------------------------------------------------------------
#define ABUF2 (128*20)
#define BBUF2 (4*128*4)
#define GBUF2 (ABUF2 + BBUF2)

__global__ __launch_bounds__(256, 2)
void gemm_tc(const float* __restrict__ Ap,
             const float* __restrict__ Wa, const float* __restrict__ Wb,
             const float* __restrict__ Wc,
             const float* __restrict__ ba, const float* __restrict__ bb,
             const float* __restrict__ bc,
             float* __restrict__ ra, float* __restrict__ rb, float* __restrict__ rc,
             float* __restrict__ pa, float* __restrict__ pb, float* __restrict__ pc,
             int modebase)
{
    extern __shared__ float2 sm2[];

    const int z = blockIdx.z;
    const float* WP   = (z == 0) ? Wa : (z == 1) ? Wb : Wc;
    const float* bias = (z == 0) ? ba : (z == 1) ? bb : bc;
    float* Craw  = (z == 0) ? ra : (z == 1) ? rb : rc;
    float* Cpair = (z == 0) ? pa : (z == 1) ? pb : pc;
    const int mode = modebase ? (1 + z) : 0;

    const int tid  = threadIdx.x;
    const int lane = tid & 31;
    const int wid  = tid >> 5;
    const int mb   = (wid >> 1) * 32;
    const int nb   = (wid & 1) * 64;
    const int lr   = lane >> 2;
    const int lc   = lane & 3;
    const int bx   = blockIdx.x;
    const int by   = blockIdx.y;

    float acc[2][8][4];
#pragma unroll
    for (int f = 0; f < 2; f++)
#pragma unroll
        for (int g = 0; g < 8; g++)
#pragma unroll
            for (int t = 0; t < 4; t++) acc[f][g][t] = 0.f;

    auto issue = [&](int kt, int buf) {
        float2* As = sm2 + buf * GBUF2;
        float2* Bs = As + ABUF2;
#pragma unroll
        for (int j = 0; j < 4; j++) {
            int idx = j * 256 + tid;
            int m   = idx >> 3;
            int ch  = idx & 7;
            cpa16(As + m * 20 + ch * 2,
                  Ap + (size_t)(by * 128 + m) * 2048 + kt * 32 + ch * 4);
        }
#pragma unroll
        for (int j = 0; j < 4; j++) {
            int idx = j * 256 + tid;
            int kb  = idx >> 8;
            int r   = idx & 255;
            int n   = r >> 1;
            int ch  = r & 1;
            cpa16(Bs + kb * 512 + n * 4 + ch * 2,
                  WP + (size_t)(kt * 4 + kb) * 16384 + (size_t)(bx * 128 + n) * 8 + ch * 4);
        }
    };

    issue(0, 0);
    CP_COMMIT;

    for (int kt = 0; kt < 64; kt++) {
        CP_WAIT0;
        __syncthreads();
        if (kt < 63) { issue(kt + 1, (kt + 1) & 1); CP_COMMIT; }

        const float2* As = sm2 + (kt & 1) * GBUF2;
        const float2* Bs = As + ABUF2;

#pragma unroll
        for (int ks = 0; ks < 4; ks++) {
            const float2* ap = As + (mb + lr) * 20 + ks * 4 + lc;
            float2 x00 = ap[0], x01 = ap[160], x10 = ap[320], x11 = ap[480];
            uint32_t a0[4] = {u32(x00.x), u32(x01.x), u32(x00.y), u32(x01.y)};
            uint32_t a1[4] = {u32(x10.x), u32(x11.x), u32(x10.y), u32(x11.y)};
            const float2* bp = Bs + ks * 512 + (nb + lr) * 4 + lc;
#pragma unroll
            for (int g = 0; g < 8; g++) {
                float2 bv = bp[g * 32];
                uint32_t b[2] = {u32(bv.x), u32(bv.y)};
                mma8(acc[0][g], a0, b);
                mma8(acc[1][g], a1, b);
            }
        }
        __syncthreads();
    }

    const float qscale = 0.08838834764831845f;   // folded into Q when mode==1
#pragma unroll
    for (int f = 0; f < 2; f++) {
#pragma unroll
        for (int g = 0; g < 8; g++) {
#pragma unroll
            for (int ii = 0; ii < 2; ii++) {
                int row = by * 128 + mb + f * 16 + lr + 8 * ii;
#pragma unroll
                for (int jj = 0; jj < 2; jj++) {
                    int col = bx * 128 + nb + g * 8 + lc * 2 + jj;
                    float v = acc[f][g][ii * 2 + jj] + bias[col];
                    if (mode == 0) {
                        Craw[(size_t)row * Dd + col] = v;
                    } else {
                        int b_ = row >> 11, s_ = row & 2047;
                        int h_ = col >> 7,  d_ = col & 127;
                        size_t bh = (size_t)(b_ * Hh + h_);
                        if (mode >= 2) Craw[(bh * Ss + s_) * HD + d_] = v;
                        if (mode == 3) {
                            Cpair[(bh * 128 + d_) * 2048 +
                                  (s_ >> 3) * 8 + (s_ & 3) * 2 + ((s_ >> 2) & 1)] = to_tf32(v);
                        } else {
                            float tv = (mode == 1) ? to_tf32(v * qscale) : to_tf32(v);
                            Cpair[(bh * Ss + s_) * 128 +
                                  (d_ >> 3) * 8 + (d_ & 3) * 2 + ((d_ >> 2) & 1)] = tv;
                        }
                    }
                }
            }
        }
    }
}

// ---------------------------------------------------------------------------
// Single-pass tf32 flash attention (R7, verified).
// ---------------------------------------------------------------------------
#define QS2 68
#define KS2 68
#define VS2 36
#define SQ2 (128*QS2)
#define SK2 (64*KS2)
#define SV2 (128*VS2)

__global__ __launch_bounds__(256)
void attn_tc(const float* __restrict__ QP, const float* __restrict__ KP,
             const float* __restrict__ VP, float* __restrict__ AP)
{
    extern __shared__ float2 sm2[];
    float2* sQ = sm2;
    float2* sK = sQ + SQ2;
    float2* sV = sK + 2 * SK2;

    const int qt  = (gridDim.x - 1) - blockIdx.x;
    const int bh  = blockIdx.y;
    const int tid = threadIdx.x;
    const int lane = tid & 31;
    const int wid  = tid >> 5;
    const int lr   = lane >> 2;
    const int lc   = lane & 3;
    const int m_off = wid * 16;

    const float* Qg = QP + ((size_t)bh * Ss + (size_t)qt * 128) * 128;
    const float* Kg = KP + (size_t)bh * Ss * 128;
    const float* Vg = VP + (size_t)bh * 128 * 2048;

#pragma unroll
    for (int i = 0; i < 16; i++) {
        int idx = i * 256 + tid;
        int row = idx >> 5;
        int ch  = idx & 31;
        cpa16(sQ + row * QS2 + ch * 2, Qg + (size_t)row * 128 + ch * 4);
    }
    CP_COMMIT;
#pragma unroll
    for (int i = 0; i < 8; i++) {
        int idx = i * 256 + tid;
        int row = idx >> 5;
        int ch  = idx & 31;
        cpa16(sK + row * KS2 + ch * 2, Kg + (size_t)row * 128 + ch * 4);
    }
#pragma unroll
    for (int i = 0; i < 8; i++) {
        int idx = i * 256 + tid;
        int d   = idx >> 4;
        int ch  = idx & 15;
        cpa16(sV + d * VS2 + ch * 2, Vg + (size_t)d * 2048 + ch * 4);
    }
    CP_COMMIT;

    CP_WAIT1;
    __syncthreads();
    uint32_t qf[16][4];
#pragma unroll
    for (int ks = 0; ks < 16; ks++) {
        const float2* qp = sQ + (m_off + lr) * QS2 + ks * 4 + lc;
        float2 q0 = qp[0], q1 = qp[8 * QS2];
        qf[ks][0] = u32(q0.x); qf[ks][1] = u32(q1.x);
        qf[ks][2] = u32(q0.y); qf[ks][3] = u32(q1.y);
    }

    float o[16][4];
#pragma unroll
    for (int n = 0; n < 16; n++)
#pragma unroll
        for (int j = 0; j < 4; j++) o[n][j] = 0.f;
    float m0 = -1e30f, m1 = -1e30f, l0 = 0.f, l1 = 0.f;

    const int tmax = 2 * qt + 1;
    const int warp_max_row = qt * 128 + m_off + 15;

    for (int t = 0; t <= tmax; t++) {
        const int buf = t & 1;
        if (t < tmax) {
            const int nb2 = (t + 1) & 1;
            float2* dK = sK + nb2 * SK2;
            float2* dV = sV + nb2 * SV2;
            const float* gK = Kg + (size_t)(t + 1) * 64 * 128;
            const float* gV = Vg + (size_t)(t + 1) * 64;
#pragma unroll
            for (int i = 0; i < 8; i++) {
                int idx = i * 256 + tid;
                int row = idx >> 5;
                int ch  = idx & 31;
                cpa16(dK + row * KS2 + ch * 2, gK + (size_t)row * 128 + ch * 4);
            }
#pragma unroll
            for (int i = 0; i < 8; i++) {
                int idx = i * 256 + tid;
                int d   = idx >> 4;
                int ch  = idx & 15;
                cpa16(dV + d * VS2 + ch * 2, gV + (size_t)d * 2048 + ch * 4);
            }
            CP_COMMIT;
            CP_WAIT1;
        } else {
            CP_WAIT0;
        }
        __syncthreads();

        if (t * 64 <= warp_max_row) {
            const float2* sKb = sK + buf * SK2;
            const float2* sVb = sV + buf * SV2;

            float c[8][4];
#pragma unroll
            for (int n = 0; n < 8; n++)
#pragma unroll
                for (int j = 0; j < 4; j++) c[n][j] = 0.f;

#pragma unroll
            for (int ks = 0; ks < 16; ks++) {
                const float2* kp = sKb + lr * KS2 + ks * 4 + lc;
#pragma unroll
                for (int nf = 0; nf < 8; nf++) {
                    float2 bv = kp[nf * 8 * KS2];
                    uint32_t b[2] = {u32(bv.x), u32(bv.y)};
                    mma8(c[nf], qf[ks], b);
                }
            }

            if (t * 64 + 63 > qt * 128 + m_off) {
#pragma unroll
                for (int nf = 0; nf < 8; nf++) {
#pragma unroll
                    for (int j = 0; j < 4; j++) {
                        int col = t * 64 + nf * 8 + 2 * lc + (j & 1);
                        int row = qt * 128 + m_off + lr + 8 * (j >> 1);
                        if (col > row) c[nf][j] = -1e30f;
                    }
                }
            }

            float mt0 = -1e30f, mt1 = -1e30f;
#pragma unroll
            for (int nf = 0; nf < 8; nf++) {
                mt0 = fmaxf(mt0, fmaxf(c[nf][0], c[nf][1]));
                mt1 = fmaxf(mt1, fmaxf(c[nf][2], c[nf][3]));
            }
#pragma unroll
            for (int d = 1; d <= 2; d <<= 1) {
                mt0 = fmaxf(mt0, __shfl_xor_sync(0xffffffffu, mt0, d));
                mt1 = fmaxf(mt1, __shfl_xor_sync(0xffffffffu, mt1, d));
            }
            float nm0 = fmaxf(m0, mt0), nm1 = fmaxf(m1, mt1);
            float corr0 = __expf(m0 - nm0), corr1 = __expf(m1 - nm1);
            m0 = nm0; m1 = nm1;

            float s0 = 0.f, s1 = 0.f;
#pragma unroll
            for (int nf = 0; nf < 8; nf++) {
                c[nf][0] = __expf(c[nf][0] - nm0); s0 += c[nf][0];
                c[nf][1] = __expf(c[nf][1] - nm0); s0 += c[nf][1];
                c[nf][2] = __expf(c[nf][2] - nm1); s1 += c[nf][2];
                c[nf][3] = __expf(c[nf][3] - nm1); s1 += c[nf][3];
            }
#pragma unroll
            for (int d = 1; d <= 2; d <<= 1) {
                s0 += __shfl_xor_sync(0xffffffffu, s0, d);
                s1 += __shfl_xor_sync(0xffffffffu, s1, d);
            }
            l0 = l0 * corr0 + s0;
            l1 = l1 * corr1 + s1;

            if (__any_sync(0xffffffffu, (corr0 != 1.f) || (corr1 != 1.f))) {
#pragma unroll
                for (int n = 0; n < 16; n++) {
                    o[n][0] *= corr0; o[n][1] *= corr0;
                    o[n][2] *= corr1; o[n][3] *= corr1;
                }
            }

#pragma unroll
            for (int ks = 0; ks < 8; ks++) {
                const int src0 = 4 * lr + (lc >> 1);
                const int src1 = src0 + 2;
                float v00 = __shfl_sync(0xffffffffu, c[ks][0], src0);
                float v01 = __shfl_sync(0xffffffffu, c[ks][1], src0);
                float v20 = __shfl_sync(0xffffffffu, c[ks][2], src0);
                float v21 = __shfl_sync(0xffffffffu, c[ks][3], src0);
                float w00 = __shfl_sync(0xffffffffu, c[ks][0], src1);
                float w01 = __shfl_sync(0xffffffffu, c[ks][1], src1);
                float w20 = __shfl_sync(0xffffffffu, c[ks][2], src1);
                float w21 = __shfl_sync(0xffffffffu, c[ks][3], src1);
                float a0f = (lc & 1) ? v01 : v00;
                float a1f = (lc & 1) ? v21 : v20;
                float a2f = (lc & 1) ? w01 : w00;
                float a3f = (lc & 1) ? w21 : w20;
                uint32_t a[4] = {u32(to_tf32(a0f)), u32(to_tf32(a1f)),
                                 u32(to_tf32(a2f)), u32(to_tf32(a3f))};
                const float2* vp = sVb + lr * VS2 + ks * 4 + lc;
#pragma unroll
                for (int nf = 0; nf < 16; nf++) {
                    float2 bv = vp[nf * 8 * VS2];
                    uint32_t b[2] = {u32(bv.x), u32(bv.y)};
                    mma8(o[nf], a, b);
                }
            }
        }
        __syncthreads();
    }

    // epilogue: normalize, convert, write pre-paired AP
    const float inv0 = 1.0f / l0;
    const float inv1 = 1.0f / l1;
    const int b = bh / Hh;
    const int h = bh % Hh;
    const size_t mrow0 = (size_t)b * 2048 + qt * 128 + m_off + lr;
    const size_t mrow1 = mrow0 + 8;
#pragma unroll
    for (int nf = 0; nf < 16; nf++) {
#pragma unroll
        for (int jj = 0; jj < 2; jj++) {
            int dl = 2 * lc + jj;
            size_t cslot = (size_t)(h * 16 + nf) * 8 + (dl & 3) * 2 + (dl >> 2);
            AP[mrow0 * 2048 + cslot] = to_tf32(o[nf][jj] * inv0);
            AP[mrow1 * 2048 + cslot] = to_tf32(o[nf][2 + jj] * inv1);
        }
    }
}

// ---------------------------------------------------------------------------

extern "C" void kernel_launch(void* const* d_in, const int* in_sizes, int n_in,
                              void* d_out, int out_size)
{
    const float* x  = (const float*)d_in[0];
    const float* Wq = (const float*)d_in[1];
    const float* bq = (const float*)d_in[2];
    const float* Wk = (const float*)d_in[3];
    const float* bk = (const float*)d_in[4];
    const float* Wv = (const float*)d_in[5];
    const float* bv = (const float*)d_in[6];
    const float* Wd = (const float*)d_in[7];
    const float* bd = (const float*)d_in[8];

    float* out = (float*)d_out;
    float* a_out = out;
    float* k_out = out + (size_t)Bb * Ss * Dd;
    float* v_out = k_out + (size_t)Bb * Ss * Dd;

    float *xp, *wpq, *wpk, *wpv, *wpd, *qp, *kp, *vp, *ap;
    cudaGetSymbolAddress((void**)&xp,  g_XP);
    cudaGetSymbolAddress((void**)&wpq, g_WPq);
    cudaGetSymbolAddress((void**)&wpk, g_WPk);
    cudaGetSymbolAddress((void**)&wpv, g_WPv);
    cudaGetSymbolAddress((void**)&wpd, g_WPd);
    cudaGetSymbolAddress((void**)&qp,  g_QP);
    cudaGetSymbolAddress((void**)&kp,  g_KP);
    cudaGetSymbolAddress((void**)&vp,  g_VP);
    cudaGetSymbolAddress((void**)&ap,  g_AP);

    xprep<<<Mtot, 256>>>(x, xp);
    wprep4<<<dim3(8, 256, 4), 256>>>(Wq, Wk, Wv, Wd, wpq, wpk, wpv, wpd);

    size_t gsm = 2 * (size_t)GBUF2 * sizeof(float2);
    cudaFuncSetAttribute(gemm_tc, cudaFuncAttributeMaxDynamicSharedMemorySize, (int)gsm);

    // fused QKV: grid.z selects (Wq,Wk,Wv); modes 1,2,3
    gemm_tc<<<dim3(Dd / 128, Mtot / 128, 3), 256, gsm>>>(
        xp, wpq, wpk, wpv, bq, bk, bv,
        nullptr, k_out, v_out, qp, kp, vp, 1);

    size_t asm_ = (size_t)(SQ2 + 2 * SK2 + 2 * SV2) * sizeof(float2);
    cudaFuncSetAttribute(attn_tc, cudaFuncAttributeMaxDynamicSharedMemorySize, (int)asm_);
    attn_tc<<<dim3(Ss / 128, Bb * Hh), 256, asm_>>>(qp, kp, vp, ap);

    // final projection: mode 0
    gemm_tc<<<dim3(Dd / 128, Mtot / 128, 1), 256, gsm>>>(
        ap, wpd, wpd, wpd, bd, bd, bd,
        a_out, a_out, a_out, nullptr, nullptr, nullptr, 0);
}

// round 13
// speedup vs baseline: 1.9915x; 1.7526x over previous
#include <cuda_runtime.h>
#include <cuda_fp16.h>
#include <cstdint>

#define Bb 2
#define Ss 2048
#define Dd 2048
#define Hh 16
#define HD 128
#define Mtot (Bb*Ss)

// fp16 pair-layout scratch (half2 stored as uint32_t).
// Row of K halfs -> K/2 half2, grouped in 16-k blocks (8 half2); within a
// block, half2 j (covering k=2j,2j+1; j local 0..7) is stored at position
// pos(j) = (j&3)*2 + (j>>2). A thread (lc) reads positions {2lc,2lc+1} as one
// LDS.64 = exactly the m16n8k16 klo/khi fragment pair.
// XPh/APh: [Mtot][1024]
// WPh:     [128 kb][2048 n][8]
// QPh/KPh: [bh=32][s=2048][64]  -> 4,194,304 u32   (R11 bug: was Mtot*64)
// VPh:     [bh=32][128 d][1024] -> 4,194,304 u32   (pairs along s)
__device__ uint32_t g_XPh[(size_t)Mtot * 1024];
__device__ uint32_t g_WPq[(size_t)128 * 2048 * 8];
__device__ uint32_t g_WPk[(size_t)128 * 2048 * 8];
__device__ uint32_t g_WPv[(size_t)128 * 2048 * 8];
__device__ uint32_t g_WPd[(size_t)128 * 2048 * 8];
__device__ uint32_t g_QPh[(size_t)Bb * Hh * Ss * 64];
__device__ uint32_t g_KPh[(size_t)Bb * Hh * Ss * 64];
__device__ uint32_t g_VPh[(size_t)Bb * Hh * 128 * 1024];
__device__ uint32_t g_APh[(size_t)Mtot * 1024];

__device__ __forceinline__ uint32_t f2h2(float a, float b) {
    __half2 h = __floats2half2_rn(a, b);   // low = a (even k), high = b
    return *(uint32_t*)&h;
}

__device__ __forceinline__ void mma16(float* c, const uint32_t* a, const uint32_t* b) {
    asm volatile(
        "mma.sync.aligned.m16n8k16.row.col.f32.f16.f16.f32 "
        "{%0,%1,%2,%3}, {%4,%5,%6,%7}, {%8,%9}, {%0,%1,%2,%3};"
        : "+f"(c[0]), "+f"(c[1]), "+f"(c[2]), "+f"(c[3])
        : "r"(a[0]), "r"(a[1]), "r"(a[2]), "r"(a[3]), "r"(b[0]), "r"(b[1]));
}
__device__ __forceinline__ void cpa16(void* dst, const void* src) {
    uint32_t d = (uint32_t)__cvta_generic_to_shared(dst);
    asm volatile("cp.async.cg.shared.global [%0], [%1], 16;" :: "r"(d), "l"(src));
}
#define CP_COMMIT asm volatile("cp.async.commit_group;")
#define CP_WAIT1  asm volatile("cp.async.wait_group 1;")
#define CP_WAIT0  asm volatile("cp.async.wait_group 0;")

// pair position of half2 j (local 0..7) within its 16-k block
__device__ __forceinline__ int ppos(int jl) { return (jl & 3) * 2 + ((jl >> 2) & 1); }

// ---------------------------------------------------------------------------
// Prep: x rows -> fp16 pair layout
// ---------------------------------------------------------------------------
__global__ void xprep_h(const float* __restrict__ X, uint32_t* __restrict__ XP) {
    __shared__ float s[2048];
    const int m = blockIdx.x;
    const int tid = threadIdx.x;
    const float* src = X + (size_t)m * 2048;
#pragma unroll
    for (int i = 0; i < 2; i++) {
        int f = i * 256 + tid;
        *(float4*)(s + f * 4) = *(const float4*)(src + f * 4);
    }
    __syncthreads();
    const int b = tid >> 1;
    const int w0 = (tid & 1) * 4;
    uint32_t o[4];
#pragma unroll
    for (int q = 0; q < 4; q++) {
        int w = w0 + q;
        int j = b * 8 + (w >> 1) + (w & 1) * 4;
        o[q] = f2h2(s[2 * j], s[2 * j + 1]);
    }
    *(uint4*)(XP + (size_t)m * 1024 + tid * 4) = make_uint4(o[0], o[1], o[2], o[3]);
}

// W[K][N] -> WPh[kb][n][8]
__global__ void wprep4_h(const float* __restrict__ W0, const float* __restrict__ W1,
                         const float* __restrict__ W2, const float* __restrict__ W3,
                         uint32_t* __restrict__ P0, uint32_t* __restrict__ P1,
                         uint32_t* __restrict__ P2, uint32_t* __restrict__ P3) {
    __shared__ float s[16 * 260];
    const int n0 = blockIdx.x * 256;
    const int kb = blockIdx.y;                 // 0..127
    const int z  = blockIdx.z;
    const int tid = threadIdx.x;
    const float* W = (z == 0) ? W0 : (z == 1) ? W1 : (z == 2) ? W2 : W3;
    uint32_t* WP   = (z == 0) ? P0 : (z == 1) ? P1 : (z == 2) ? P2 : P3;
#pragma unroll
    for (int i = 0; i < 4; i++) {
        int f = i * 256 + tid;
        int r = f >> 6, c4 = (f & 63) * 4;
        float4 v = *(const float4*)(W + (size_t)(kb * 16 + r) * 2048 + n0 + c4);
        *(float4*)(s + r * 260 + c4) = v;
    }
    __syncthreads();
    const int n = tid;
    uint32_t o[8];
#pragma unroll
    for (int w = 0; w < 8; w++) {
        int j = (w >> 1) + (w & 1) * 4;
        o[w] = f2h2(s[(2 * j) * 260 + n], s[(2 * j + 1) * 260 + n]);
    }
    uint32_t* dst = WP + ((size_t)kb * 2048 + n0 + n) * 8;
    *(uint4*)(dst)     = make_uint4(o[0], o[1], o[2], o[3]);
    *(uint4*)(dst + 4) = make_uint4(o[4], o[5], o[6], o[7]);
}

// ---------------------------------------------------------------------------
// fp16 tensor-core GEMM, BK=32 (2 k16), 2-stage cp.async, fused via grid.z.
// BM=BN=128, 8 warps (4m x 2n), warp 32x64.
// As: [128 m][24 u32] (16 data + 8 pad; stride%32==8 -> CF frag LDS.64)
// Bs: [2 kb][128 n][8 u32]
// modes: 0 plain fp32 C; 1 Q->QPh (qscale); 2 K->k_out+KPh; 3 V->v_out+VPh
// ---------------------------------------------------------------------------
#define HASTR 24
#define HABUF (128 * HASTR)
#define HBBUF (2 * 128 * 8)
#define HGBUF (HABUF + HBBUF)

__global__ __launch_bounds__(256, 2)
void gemm_h(const uint32_t* __restrict__ Ap,
            const uint32_t* __restrict__ Wa, const uint32_t* __restrict__ Wb,
            const uint32_t* __restrict__ Wc,
            const float* __restrict__ ba, const float* __restrict__ bb,
            const float* __restrict__ bc,
            float* __restrict__ ra, float* __restrict__ rb, float* __restrict__ rc,
            uint32_t* __restrict__ pa, uint32_t* __restrict__ pb, uint32_t* __restrict__ pc,
            int modebase)
{
    extern __shared__ uint32_t smu[];

    const int z = blockIdx.z;
    const uint32_t* WP = (z == 0) ? Wa : (z == 1) ? Wb : Wc;
    const float* bias  = (z == 0) ? ba : (z == 1) ? bb : bc;
    float* Craw        = (z == 0) ? ra : (z == 1) ? rb : rc;
    uint32_t* Cpair    = (z == 0) ? pa : (z == 1) ? pb : pc;
    const int mode = modebase ? (1 + z) : 0;

    const int tid  = threadIdx.x;
    const int lane = tid & 31;
    const int wid  = tid >> 5;
    const int mb   = (wid >> 1) * 32;
    const int nb   = (wid & 1) * 64;
    const int lr   = lane >> 2;
    const int lc   = lane & 3;
    const int bx   = blockIdx.x;
    const int by   = blockIdx.y;

    float acc[2][8][4];
#pragma unroll
    for (int f = 0; f < 2; f++)
#pragma unroll
        for (int g = 0; g < 8; g++)
#pragma unroll
            for (int t = 0; t < 4; t++) acc[f][g][t] = 0.f;

    auto issue = [&](int kt, int buf) {
        uint32_t* As = smu + buf * HGBUF;
        uint32_t* Bs = As + HABUF;
#pragma unroll
        for (int j = 0; j < 2; j++) {
            int idx = j * 256 + tid;
            int m = idx >> 2, ch = idx & 3;
            cpa16(As + m * HASTR + ch * 4,
                  Ap + (size_t)(by * 128 + m) * 1024 + kt * 16 + ch * 4);
        }
#pragma unroll
        for (int j = 0; j < 2; j++) {
            int idx = j * 256 + tid;
            int kb = idx >> 8, r = idx & 255, n = r >> 1, ch = r & 1;
            cpa16(Bs + kb * 1024 + n * 8 + ch * 4,
                  WP + ((size_t)(kt * 2 + kb) * 2048 + bx * 128 + n) * 8 + ch * 4);
        }
    };

    issue(0, 0);
    CP_COMMIT;

    for (int kt = 0; kt < 64; kt++) {
        CP_WAIT0;
        __syncthreads();
        if (kt < 63) { issue(kt + 1, (kt + 1) & 1); CP_COMMIT; }

        const uint32_t* As = smu + (kt & 1) * HGBUF;
        const uint32_t* Bs = As + HABUF;

#pragma unroll
        for (int kb = 0; kb < 2; kb++) {
            const int ao = kb * 8 + 2 * lc;
            uint2 x0 = *(const uint2*)(As + (mb + lr) * HASTR + ao);
            uint2 x1 = *(const uint2*)(As + (mb + lr + 8) * HASTR + ao);
            uint2 x2 = *(const uint2*)(As + (mb + 16 + lr) * HASTR + ao);
            uint2 x3 = *(const uint2*)(As + (mb + 24 + lr) * HASTR + ao);
            uint32_t a0[4] = {x0.x, x1.x, x0.y, x1.y};
            uint32_t a1[4] = {x2.x, x3.x, x2.y, x3.y};
            const uint32_t* bp = Bs + kb * 1024 + (nb + lr) * 8 + 2 * lc;
#pragma unroll
            for (int g = 0; g < 8; g++) {
                uint2 bv = *(const uint2*)(bp + g * 64);
                uint32_t b[2] = {bv.x, bv.y};
                mma16(acc[0][g], a0, b);
                mma16(acc[1][g], a1, b);
            }
        }
        __syncthreads();
    }

    const float qscale = 0.08838834764831845f;
#pragma unroll
    for (int f = 0; f < 2; f++) {
#pragma unroll
        for (int g = 0; g < 8; g++) {
#pragma unroll
            for (int ii = 0; ii < 2; ii++) {
                int row = by * 128 + mb + f * 16 + lr + 8 * ii;
                int col0 = bx * 128 + nb + g * 8 + lc * 2;
                float v0 = acc[f][g][ii * 2 + 0] + bias[col0];
                float v1 = acc[f][g][ii * 2 + 1] + bias[col0 + 1];
                if (mode == 0) {
                    float* p = Craw + (size_t)row * Dd + col0;
                    p[0] = v0; p[1] = v1;
                } else {
                    int b_ = row >> 11, s_ = row & 2047;
                    int h_ = col0 >> 7, d_ = col0 & 127;
                    size_t bh = (size_t)(b_ * Hh + h_);
                    if (mode >= 2) {
                        float* p = Craw + (bh * Ss + s_) * HD + d_;
                        p[0] = v0; p[1] = v1;
                    }
                    if (mode == 3) {
                        // pair along s via row-pair shfl (rows lr, lr^1)
                        float u0 = __shfl_xor_sync(0xffffffffu, v0, 4);
                        float u1 = __shfl_xor_sync(0xffffffffu, v1, 4);
                        if (!(lr & 1)) {
                            int js = s_ >> 1;
                            size_t slot = (size_t)(js >> 3) * 8 + ppos(js & 7);
                            Cpair[(bh * 128 + d_) * 1024 + slot]       = f2h2(v0, u0);
                            Cpair[(bh * 128 + d_ + 1) * 1024 + slot]   = f2h2(v1, u1);
                        }
                    } else {
                        float s0 = (mode == 1) ? v0 * qscale : v0;
                        float s1 = (mode == 1) ? v1 * qscale : v1;
                        int j = d_ >> 1;
                        Cpair[(bh * Ss + s_) * 64 + (j >> 3) * 8 + ppos(j & 7)] = f2h2(s0, s1);
                    }
                }
            }
        }
    }
}

// ---------------------------------------------------------------------------
// fp16 flash attention. Grid (S/128, B*H), 8 warps x 16 q-rows, KV tiles 64.
// S-accumulator layout == P A-fragment layout: no shuffles in PV.
// sQ [128][72], sK 2x[64][72], sV 2x[128][40]  (u32 = half2 units), 112 KB
// ---------------------------------------------------------------------------
#define HQS 72
#define HKS 72
#define HVS 40
#define HSQ (128 * HQS)
#define HSK (64 * HKS)
#define HSV (128 * HVS)

__global__ __launch_bounds__(256)
void attn_h(const uint32_t* __restrict__ QP, const uint32_t* __restrict__ KP,
            const uint32_t* __restrict__ VP, uint32_t* __restrict__ AP)
{
    extern __shared__ uint32_t smu[];
    uint32_t* sQ = smu;
    uint32_t* sK = sQ + HSQ;
    uint32_t* sV = sK + 2 * HSK;

    const int qt  = (gridDim.x - 1) - blockIdx.x;
    const int bh  = blockIdx.y;
    const int tid = threadIdx.x;
    const int lane = tid & 31;
    const int wid  = tid >> 5;
    const int lr   = lane >> 2;
    const int lc   = lane & 3;
    const int m_off = wid * 16;

    const uint32_t* Qg = QP + ((size_t)bh * Ss + (size_t)qt * 128) * 64;
    const uint32_t* Kg = KP + (size_t)bh * Ss * 64;
    const uint32_t* Vg = VP + (size_t)bh * 128 * 1024;

    // group 0: Q (128 rows x 16 chunks)
#pragma unroll
    for (int i = 0; i < 8; i++) {
        int idx = i * 256 + tid;
        int row = idx >> 4, ch = idx & 15;
        cpa16(sQ + row * HQS + ch * 4, Qg + (size_t)row * 64 + ch * 4);
    }
    CP_COMMIT;
    // group 1: KV tile 0
#pragma unroll
    for (int i = 0; i < 4; i++) {
        int idx = i * 256 + tid;
        int row = idx >> 4, ch = idx & 15;
        cpa16(sK + row * HKS + ch * 4, Kg + (size_t)row * 64 + ch * 4);
    }
#pragma unroll
    for (int i = 0; i < 4; i++) {
        int idx = i * 256 + tid;
        int d = idx >> 3, ch = idx & 7;
        cpa16(sV + d * HVS + ch * 4, Vg + (size_t)d * 1024 + ch * 4);
    }
    CP_COMMIT;

    CP_WAIT1;
    __syncthreads();
    uint32_t qf[8][4];
#pragma unroll
    for (int kb = 0; kb < 8; kb++) {
        uint2 q0 = *(const uint2*)(sQ + (m_off + lr) * HQS + kb * 8 + 2 * lc);
        uint2 q1 = *(const uint2*)(sQ + (m_off + lr + 8) * HQS + kb * 8 + 2 * lc);
        qf[kb][0] = q0.x; qf[kb][1] = q1.x; qf[kb][2] = q0.y; qf[kb][3] = q1.y;
    }

    float o[16][4];
#pragma unroll
    for (int n = 0; n < 16; n++)
#pragma unroll
        for (int j = 0; j < 4; j++) o[n][j] = 0.f;
    float m0 = -1e30f, m1 = -1e30f, l0 = 0.f, l1 = 0.f;

    const int tmax = 2 * qt + 1;
    const int warp_max_row = qt * 128 + m_off + 15;

    for (int t = 0; t <= tmax; t++) {
        const int buf = t & 1;
        if (t < tmax) {
            const int nb2 = (t + 1) & 1;
            uint32_t* dK = sK + nb2 * HSK;
            uint32_t* dV = sV + nb2 * HSV;
            const uint32_t* gK = Kg + (size_t)(t + 1) * 64 * 64;
            const uint32_t* gV = Vg + (size_t)(t + 1) * 32;
#pragma unroll
            for (int i = 0; i < 4; i++) {
                int idx = i * 256 + tid;
                int row = idx >> 4, ch = idx & 15;
                cpa16(dK + row * HKS + ch * 4, gK + (size_t)row * 64 + ch * 4);
            }
#pragma unroll
            for (int i = 0; i < 4; i++) {
                int idx = i * 256 + tid;
                int d = idx >> 3, ch = idx & 7;
                cpa16(dV + d * HVS + ch * 4, gV + (size_t)d * 1024 + ch * 4);
            }
            CP_COMMIT;
            CP_WAIT1;
        } else {
            CP_WAIT0;
        }
        __syncthreads();

        if (t * 64 <= warp_max_row) {
            const uint32_t* sKb = sK + buf * HSK;
            const uint32_t* sVb = sV + buf * HSV;

            // ---- S = Q @ K^T ----
            float c[8][4];
#pragma unroll
            for (int n = 0; n < 8; n++)
#pragma unroll
                for (int j = 0; j < 4; j++) c[n][j] = 0.f;

#pragma unroll
            for (int kb = 0; kb < 8; kb++) {
                const uint32_t* kp = sKb + lr * HKS + kb * 8 + 2 * lc;
#pragma unroll
                for (int nf = 0; nf < 8; nf++) {
                    uint2 kv = *(const uint2*)(kp + nf * 8 * HKS);
                    uint32_t b[2] = {kv.x, kv.y};
                    mma16(c[nf], qf[kb], b);
                }
            }

            // ---- causal mask ----
            if (t * 64 + 63 > qt * 128 + m_off) {
#pragma unroll
                for (int nf = 0; nf < 8; nf++) {
#pragma unroll
                    for (int j = 0; j < 4; j++) {
                        int col = t * 64 + nf * 8 + 2 * lc + (j & 1);
                        int row = qt * 128 + m_off + lr + 8 * (j >> 1);
                        if (col > row) c[nf][j] = -1e30f;
                    }
                }
            }

            // ---- online softmax (rows lr, lr+8) ----
            float mt0 = -1e30f, mt1 = -1e30f;
#pragma unroll
            for (int nf = 0; nf < 8; nf++) {
                mt0 = fmaxf(mt0, fmaxf(c[nf][0], c[nf][1]));
                mt1 = fmaxf(mt1, fmaxf(c[nf][2], c[nf][3]));
            }
#pragma unroll
            for (int d = 1; d <= 2; d <<= 1) {
                mt0 = fmaxf(mt0, __shfl_xor_sync(0xffffffffu, mt0, d));
                mt1 = fmaxf(mt1, __shfl_xor_sync(0xffffffffu, mt1, d));
            }
            float nm0 = fmaxf(m0, mt0), nm1 = fmaxf(m1, mt1);
            float corr0 = __expf(m0 - nm0), corr1 = __expf(m1 - nm1);
            m0 = nm0; m1 = nm1;

            float s0 = 0.f, s1 = 0.f;
#pragma unroll
            for (int nf = 0; nf < 8; nf++) {
                c[nf][0] = __expf(c[nf][0] - nm0); s0 += c[nf][0];
                c[nf][1] = __expf(c[nf][1] - nm0); s0 += c[nf][1];
                c[nf][2] = __expf(c[nf][2] - nm1); s1 += c[nf][2];
                c[nf][3] = __expf(c[nf][3] - nm1); s1 += c[nf][3];
            }
#pragma unroll
            for (int d = 1; d <= 2; d <<= 1) {
                s0 += __shfl_xor_sync(0xffffffffu, s0, d);
                s1 += __shfl_xor_sync(0xffffffffu, s1, d);
            }
            l0 = l0 * corr0 + s0;
            l1 = l1 * corr1 + s1;

            if (__any_sync(0xffffffffu, (corr0 != 1.f) || (corr1 != 1.f))) {
#pragma unroll
                for (int n = 0; n < 16; n++) {
                    o[n][0] *= corr0; o[n][1] *= corr0;
                    o[n][2] *= corr1; o[n][3] *= corr1;
                }
            }

            // ---- O += P @ V  (C-frag layout == A-frag layout: no shfl) ----
#pragma unroll
            for (int kp2 = 0; kp2 < 4; kp2++) {
                uint32_t a[4];
                a[0] = f2h2(c[2 * kp2][0],     c[2 * kp2][1]);
                a[1] = f2h2(c[2 * kp2][2],     c[2 * kp2][3]);
                a[2] = f2h2(c[2 * kp2 + 1][0], c[2 * kp2 + 1][1]);
                a[3] = f2h2(c[2 * kp2 + 1][2], c[2 * kp2 + 1][3]);
                const uint32_t* vp = sVb + lr * HVS + kp2 * 8 + 2 * lc;
#pragma unroll
                for (int nf = 0; nf < 16; nf++) {
                    uint2 vv = *(const uint2*)(vp + nf * 8 * HVS);
                    uint32_t b[2] = {vv.x, vv.y};
                    mma16(o[nf], a, b);
                }
            }
        }
        __syncthreads();
    }

    // ---- epilogue: normalize, write APh (pair layout for final GEMM) ----
    const float inv0 = 1.0f / l0;
    const float inv1 = 1.0f / l1;
    const int b = bh / Hh;
    const int h = bh % Hh;
    const size_t mrow0 = (size_t)b * 2048 + qt * 128 + m_off + lr;
    const size_t mrow1 = mrow0 + 8;
#pragma unroll
    for (int nf = 0; nf < 16; nf++) {
        int j = h * 64 + nf * 4 + lc;
        size_t slot = (size_t)(j >> 3) * 8 + ppos(j & 7);
        AP[mrow0 * 1024 + slot] = f2h2(o[nf][0] * inv0, o[nf][1] * inv0);
        AP[mrow1 * 1024 + slot] = f2h2(o[nf][2] * inv1, o[nf][3] * inv1);
    }
}

// ---------------------------------------------------------------------------

extern "C" void kernel_launch(void* const* d_in, const int* in_sizes, int n_in,
                              void* d_out, int out_size)
{
    const float* x  = (const float*)d_in[0];
    const float* Wq = (const float*)d_in[1];
    const float* bq = (const float*)d_in[2];
    const float* Wk = (const float*)d_in[3];
    const float* bk = (const float*)d_in[4];
    const float* Wv = (const float*)d_in[5];
    const float* bv = (const float*)d_in[6];
    const float* Wd = (const float*)d_in[7];
    const float* bd = (const float*)d_in[8];

    float* out = (float*)d_out;
    float* a_out = out;
    float* k_out = out + (size_t)Bb * Ss * Dd;
    float* v_out = k_out + (size_t)Bb * Ss * Dd;

    uint32_t *xp, *wpq, *wpk, *wpv, *wpd, *qp, *kp, *vp, *ap;
    cudaGetSymbolAddress((void**)&xp,  g_XPh);
    cudaGetSymbolAddress((void**)&wpq, g_WPq);
    cudaGetSymbolAddress((void**)&wpk, g_WPk);
    cudaGetSymbolAddress((void**)&wpv, g_WPv);
    cudaGetSymbolAddress((void**)&wpd, g_WPd);
    cudaGetSymbolAddress((void**)&qp,  g_QPh);
    cudaGetSymbolAddress((void**)&kp,  g_KPh);
    cudaGetSymbolAddress((void**)&vp,  g_VPh);
    cudaGetSymbolAddress((void**)&ap,  g_APh);

    xprep_h<<<Mtot, 256>>>(x, xp);
    wprep4_h<<<dim3(8, 128, 4), 256>>>(Wq, Wk, Wv, Wd, wpq, wpk, wpv, wpd);

    size_t gsm = 2 * (size_t)HGBUF * sizeof(uint32_t);
    cudaFuncSetAttribute(gemm_h, cudaFuncAttributeMaxDynamicSharedMemorySize, (int)gsm);

    // fused QKV: z selects (Wq,Wk,Wv); modes 1,2,3
    gemm_h<<<dim3(Dd / 128, Mtot / 128, 3), 256, gsm>>>(
        xp, wpq, wpk, wpv, bq, bk, bv,
        nullptr, k_out, v_out, qp, kp, vp, 1);

    size_t asm_ = (size_t)(HSQ + 2 * HSK + 2 * HSV) * sizeof(uint32_t);
    cudaFuncSetAttribute(attn_h, cudaFuncAttributeMaxDynamicSharedMemorySize, (int)asm_);
    attn_h<<<dim3(Ss / 128, Bb * Hh), 256, asm_>>>(qp, kp, vp, ap);

    // final projection: mode 0
    gemm_h<<<dim3(Dd / 128, Mtot / 128, 1), 256, gsm>>>(
        ap, wpd, wpd, wpd, bd, bd, bd,
        a_out, a_out, a_out, nullptr, nullptr, nullptr, 0);
}

// round 14
// speedup vs baseline: 2.0120x; 1.0103x over previous
#include <cuda_runtime.h>
#include <cuda_fp16.h>
#include <cstdint>

#define Bb 2
#define Ss 2048
#define Dd 2048
#define Hh 16
#define HD 128
#define Mtot (Bb*Ss)

// fp16 pair-layout scratch (half2 stored as uint32_t).
// Row of K halfs -> K/2 half2, grouped in 16-k blocks (8 half2); within a
// block, half2 j (local 0..7) at position pos(j) = (j&3)*2 + (j>>2). A thread
// (lc) reads positions {2lc,2lc+1} as one LDS.64 = m16n8k16 klo/khi pair.
// XPh/APh: [Mtot][1024]
// WPh:     [128 kb][2048 n][8]
// QPh/KPh: [bh=32][s=2048][64]
// VPh:     [bh=32][128 d][1024]  (pairs along s)
__device__ uint32_t g_XPh[(size_t)Mtot * 1024];
__device__ uint32_t g_WPq[(size_t)128 * 2048 * 8];
__device__ uint32_t g_WPk[(size_t)128 * 2048 * 8];
__device__ uint32_t g_WPv[(size_t)128 * 2048 * 8];
__device__ uint32_t g_WPd[(size_t)128 * 2048 * 8];
__device__ uint32_t g_QPh[(size_t)Bb * Hh * Ss * 64];
__device__ uint32_t g_KPh[(size_t)Bb * Hh * Ss * 64];
__device__ uint32_t g_VPh[(size_t)Bb * Hh * 128 * 1024];
__device__ uint32_t g_APh[(size_t)Mtot * 1024];

__device__ __forceinline__ uint32_t f2h2(float a, float b) {
    __half2 h = __floats2half2_rn(a, b);
    return *(uint32_t*)&h;
}

__device__ __forceinline__ void mma16(float* c, const uint32_t* a, const uint32_t* b) {
    asm volatile(
        "mma.sync.aligned.m16n8k16.row.col.f32.f16.f16.f32 "
        "{%0,%1,%2,%3}, {%4,%5,%6,%7}, {%8,%9}, {%0,%1,%2,%3};"
        : "+f"(c[0]), "+f"(c[1]), "+f"(c[2]), "+f"(c[3])
        : "r"(a[0]), "r"(a[1]), "r"(a[2]), "r"(a[3]), "r"(b[0]), "r"(b[1]));
}
__device__ __forceinline__ void cpa16(void* dst, const void* src) {
    uint32_t d = (uint32_t)__cvta_generic_to_shared(dst);
    asm volatile("cp.async.cg.shared.global [%0], [%1], 16;" :: "r"(d), "l"(src));
}
#define CP_COMMIT asm volatile("cp.async.commit_group;")
#define CP_WAIT1  asm volatile("cp.async.wait_group 1;")
#define CP_WAIT0  asm volatile("cp.async.wait_group 0;")

__device__ __forceinline__ int ppos(int jl) { return (jl & 3) * 2 + ((jl >> 2) & 1); }

// ---------------------------------------------------------------------------
// Prep kernels (R12, verified)
// ---------------------------------------------------------------------------
__global__ void xprep_h(const float* __restrict__ X, uint32_t* __restrict__ XP) {
    __shared__ float s[2048];
    const int m = blockIdx.x;
    const int tid = threadIdx.x;
    const float* src = X + (size_t)m * 2048;
#pragma unroll
    for (int i = 0; i < 2; i++) {
        int f = i * 256 + tid;
        *(float4*)(s + f * 4) = *(const float4*)(src + f * 4);
    }
    __syncthreads();
    const int b = tid >> 1;
    const int w0 = (tid & 1) * 4;
    uint32_t o[4];
#pragma unroll
    for (int q = 0; q < 4; q++) {
        int w = w0 + q;
        int j = b * 8 + (w >> 1) + (w & 1) * 4;
        o[q] = f2h2(s[2 * j], s[2 * j + 1]);
    }
    *(uint4*)(XP + (size_t)m * 1024 + tid * 4) = make_uint4(o[0], o[1], o[2], o[3]);
}

__global__ void wprep4_h(const float* __restrict__ W0, const float* __restrict__ W1,
                         const float* __restrict__ W2, const float* __restrict__ W3,
                         uint32_t* __restrict__ P0, uint32_t* __restrict__ P1,
                         uint32_t* __restrict__ P2, uint32_t* __restrict__ P3) {
    __shared__ float s[16 * 260];
    const int n0 = blockIdx.x * 256;
    const int kb = blockIdx.y;
    const int z  = blockIdx.z;
    const int tid = threadIdx.x;
    const float* W = (z == 0) ? W0 : (z == 1) ? W1 : (z == 2) ? W2 : W3;
    uint32_t* WP   = (z == 0) ? P0 : (z == 1) ? P1 : (z == 2) ? P2 : P3;
#pragma unroll
    for (int i = 0; i < 4; i++) {
        int f = i * 256 + tid;
        int r = f >> 6, c4 = (f & 63) * 4;
        float4 v = *(const float4*)(W + (size_t)(kb * 16 + r) * 2048 + n0 + c4);
        *(float4*)(s + r * 260 + c4) = v;
    }
    __syncthreads();
    const int n = tid;
    uint32_t o[8];
#pragma unroll
    for (int w = 0; w < 8; w++) {
        int j = (w >> 1) + (w & 1) * 4;
        o[w] = f2h2(s[(2 * j) * 260 + n], s[(2 * j + 1) * 260 + n]);
    }
    uint32_t* dst = WP + ((size_t)kb * 2048 + n0 + n) * 8;
    *(uint4*)(dst)     = make_uint4(o[0], o[1], o[2], o[3]);
    *(uint4*)(dst + 4) = make_uint4(o[4], o[5], o[6], o[7]);
}

// ---------------------------------------------------------------------------
// PERSISTENT fp16 tensor-core GEMM. Grid = 296 CTAs; each loops over tiles.
// Tile map: bx = t&15 (N), by = (t>>4)&31 (M), z = t>>9 (weight set).
// Inner pipeline identical to R12 (BK=32, 2-stage cp.async).
// modes: 0 plain fp32 C; 1 Q->QPh (qscale); 2 K->k_out+KPh; 3 V->v_out+VPh
// ---------------------------------------------------------------------------
#define HASTR 24
#define HABUF (128 * HASTR)
#define HBBUF (2 * 128 * 8)
#define HGBUF (HABUF + HBBUF)

__global__ __launch_bounds__(256, 2)
void gemm_h(const uint32_t* __restrict__ Ap,
            const uint32_t* __restrict__ Wa, const uint32_t* __restrict__ Wb,
            const uint32_t* __restrict__ Wc,
            const float* __restrict__ ba, const float* __restrict__ bb,
            const float* __restrict__ bc,
            float* __restrict__ ra, float* __restrict__ rb, float* __restrict__ rc,
            uint32_t* __restrict__ pa, uint32_t* __restrict__ pb, uint32_t* __restrict__ pc,
            int modebase, int ntiles)
{
    extern __shared__ uint32_t smu[];

    const int tid  = threadIdx.x;
    const int lane = tid & 31;
    const int wid  = tid >> 5;
    const int mb   = (wid >> 1) * 32;
    const int nb   = (wid & 1) * 64;
    const int lr   = lane >> 2;
    const int lc   = lane & 3;

    for (int tile = blockIdx.x; tile < ntiles; tile += gridDim.x) {
        const int bx = tile & 15;
        const int by = (tile >> 4) & 31;
        const int z  = tile >> 9;
        const uint32_t* WP = (z == 0) ? Wa : (z == 1) ? Wb : Wc;
        const float* bias  = (z == 0) ? ba : (z == 1) ? bb : bc;
        float* Craw        = (z == 0) ? ra : (z == 1) ? rb : rc;
        uint32_t* Cpair    = (z == 0) ? pa : (z == 1) ? pb : pc;
        const int mode = modebase ? (1 + z) : 0;

        float acc[2][8][4];
#pragma unroll
        for (int f = 0; f < 2; f++)
#pragma unroll
            for (int g = 0; g < 8; g++)
#pragma unroll
                for (int t = 0; t < 4; t++) acc[f][g][t] = 0.f;

        auto issue = [&](int kt, int buf) {
            uint32_t* As = smu + buf * HGBUF;
            uint32_t* Bs = As + HABUF;
#pragma unroll
            for (int j = 0; j < 2; j++) {
                int idx = j * 256 + tid;
                int m = idx >> 2, ch = idx & 3;
                cpa16(As + m * HASTR + ch * 4,
                      Ap + (size_t)(by * 128 + m) * 1024 + kt * 16 + ch * 4);
            }
#pragma unroll
            for (int j = 0; j < 2; j++) {
                int idx = j * 256 + tid;
                int kb = idx >> 8, r = idx & 255, n = r >> 1, ch = r & 1;
                cpa16(Bs + kb * 1024 + n * 8 + ch * 4,
                      WP + ((size_t)(kt * 2 + kb) * 2048 + bx * 128 + n) * 8 + ch * 4);
            }
        };

        issue(0, 0);
        CP_COMMIT;

        for (int kt = 0; kt < 64; kt++) {
            CP_WAIT0;
            __syncthreads();
            if (kt < 63) { issue(kt + 1, (kt + 1) & 1); CP_COMMIT; }

            const uint32_t* As = smu + (kt & 1) * HGBUF;
            const uint32_t* Bs = As + HABUF;

#pragma unroll
            for (int kb = 0; kb < 2; kb++) {
                const int ao = kb * 8 + 2 * lc;
                uint2 x0 = *(const uint2*)(As + (mb + lr) * HASTR + ao);
                uint2 x1 = *(const uint2*)(As + (mb + lr + 8) * HASTR + ao);
                uint2 x2 = *(const uint2*)(As + (mb + 16 + lr) * HASTR + ao);
                uint2 x3 = *(const uint2*)(As + (mb + 24 + lr) * HASTR + ao);
                uint32_t a0[4] = {x0.x, x1.x, x0.y, x1.y};
                uint32_t a1[4] = {x2.x, x3.x, x2.y, x3.y};
                const uint32_t* bp = Bs + kb * 1024 + (nb + lr) * 8 + 2 * lc;
#pragma unroll
                for (int g = 0; g < 8; g++) {
                    uint2 bv = *(const uint2*)(bp + g * 64);
                    uint32_t b[2] = {bv.x, bv.y};
                    mma16(acc[0][g], a0, b);
                    mma16(acc[1][g], a1, b);
                }
            }
            __syncthreads();
        }

        const float qscale = 0.08838834764831845f;
#pragma unroll
        for (int f = 0; f < 2; f++) {
#pragma unroll
            for (int g = 0; g < 8; g++) {
#pragma unroll
                for (int ii = 0; ii < 2; ii++) {
                    int row = by * 128 + mb + f * 16 + lr + 8 * ii;
                    int col0 = bx * 128 + nb + g * 8 + lc * 2;
                    float v0 = acc[f][g][ii * 2 + 0] + bias[col0];
                    float v1 = acc[f][g][ii * 2 + 1] + bias[col0 + 1];
                    if (mode == 0) {
                        float* p = Craw + (size_t)row * Dd + col0;
                        p[0] = v0; p[1] = v1;
                    } else {
                        int b_ = row >> 11, s_ = row & 2047;
                        int h_ = col0 >> 7, d_ = col0 & 127;
                        size_t bh = (size_t)(b_ * Hh + h_);
                        if (mode >= 2) {
                            float* p = Craw + (bh * Ss + s_) * HD + d_;
                            p[0] = v0; p[1] = v1;
                        }
                        if (mode == 3) {
                            float u0 = __shfl_xor_sync(0xffffffffu, v0, 4);
                            float u1 = __shfl_xor_sync(0xffffffffu, v1, 4);
                            if (!(lr & 1)) {
                                int js = s_ >> 1;
                                size_t slot = (size_t)(js >> 3) * 8 + ppos(js & 7);
                                Cpair[(bh * 128 + d_) * 1024 + slot]     = f2h2(v0, u0);
                                Cpair[(bh * 128 + d_ + 1) * 1024 + slot] = f2h2(v1, u1);
                            }
                        } else {
                            float s0 = (mode == 1) ? v0 * qscale : v0;
                            float s1 = (mode == 1) ? v1 * qscale : v1;
                            int j = d_ >> 1;
                            Cpair[(bh * Ss + s_) * 64 + (j >> 3) * 8 + ppos(j & 7)] = f2h2(s0, s1);
                        }
                    }
                }
            }
        }
        // epilogue touches no smem; trailing k-loop sync protects buffer reuse
    }
}

// ---------------------------------------------------------------------------
// fp16 flash attention (R12, verified at 174.9us).
// ---------------------------------------------------------------------------
#define HQS 72
#define HKS 72
#define HVS 40
#define HSQ (128 * HQS)
#define HSK (64 * HKS)
#define HSV (128 * HVS)

__global__ __launch_bounds__(256)
void attn_h(const uint32_t* __restrict__ QP, const uint32_t* __restrict__ KP,
            const uint32_t* __restrict__ VP, uint32_t* __restrict__ AP)
{
    extern __shared__ uint32_t smu[];
    uint32_t* sQ = smu;
    uint32_t* sK = sQ + HSQ;
    uint32_t* sV = sK + 2 * HSK;

    const int qt  = (gridDim.x - 1) - blockIdx.x;
    const int bh  = blockIdx.y;
    const int tid = threadIdx.x;
    const int lane = tid & 31;
    const int wid  = tid >> 5;
    const int lr   = lane >> 2;
    const int lc   = lane & 3;
    const int m_off = wid * 16;

    const uint32_t* Qg = QP + ((size_t)bh * Ss + (size_t)qt * 128) * 64;
    const uint32_t* Kg = KP + (size_t)bh * Ss * 64;
    const uint32_t* Vg = VP + (size_t)bh * 128 * 1024;

#pragma unroll
    for (int i = 0; i < 8; i++) {
        int idx = i * 256 + tid;
        int row = idx >> 4, ch = idx & 15;
        cpa16(sQ + row * HQS + ch * 4, Qg + (size_t)row * 64 + ch * 4);
    }
    CP_COMMIT;
#pragma unroll
    for (int i = 0; i < 4; i++) {
        int idx = i * 256 + tid;
        int row = idx >> 4, ch = idx & 15;
        cpa16(sK + row * HKS + ch * 4, Kg + (size_t)row * 64 + ch * 4);
    }
#pragma unroll
    for (int i = 0; i < 4; i++) {
        int idx = i * 256 + tid;
        int d = idx >> 3, ch = idx & 7;
        cpa16(sV + d * HVS + ch * 4, Vg + (size_t)d * 1024 + ch * 4);
    }
    CP_COMMIT;

    CP_WAIT1;
    __syncthreads();
    uint32_t qf[8][4];
#pragma unroll
    for (int kb = 0; kb < 8; kb++) {
        uint2 q0 = *(const uint2*)(sQ + (m_off + lr) * HQS + kb * 8 + 2 * lc);
        uint2 q1 = *(const uint2*)(sQ + (m_off + lr + 8) * HQS + kb * 8 + 2 * lc);
        qf[kb][0] = q0.x; qf[kb][1] = q1.x; qf[kb][2] = q0.y; qf[kb][3] = q1.y;
    }

    float o[16][4];
#pragma unroll
    for (int n = 0; n < 16; n++)
#pragma unroll
        for (int j = 0; j < 4; j++) o[n][j] = 0.f;
    float m0 = -1e30f, m1 = -1e30f, l0 = 0.f, l1 = 0.f;

    const int tmax = 2 * qt + 1;
    const int warp_max_row = qt * 128 + m_off + 15;

    for (int t = 0; t <= tmax; t++) {
        const int buf = t & 1;
        if (t < tmax) {
            const int nb2 = (t + 1) & 1;
            uint32_t* dK = sK + nb2 * HSK;
            uint32_t* dV = sV + nb2 * HSV;
            const uint32_t* gK = Kg + (size_t)(t + 1) * 64 * 64;
            const uint32_t* gV = Vg + (size_t)(t + 1) * 32;
#pragma unroll
            for (int i = 0; i < 4; i++) {
                int idx = i * 256 + tid;
                int row = idx >> 4, ch = idx & 15;
                cpa16(dK + row * HKS + ch * 4, gK + (size_t)row * 64 + ch * 4);
            }
#pragma unroll
            for (int i = 0; i < 4; i++) {
                int idx = i * 256 + tid;
                int d = idx >> 3, ch = idx & 7;
                cpa16(dV + d * HVS + ch * 4, gV + (size_t)d * 1024 + ch * 4);
            }
            CP_COMMIT;
            CP_WAIT1;
        } else {
            CP_WAIT0;
        }
        __syncthreads();

        if (t * 64 <= warp_max_row) {
            const uint32_t* sKb = sK + buf * HSK;
            const uint32_t* sVb = sV + buf * HSV;

            float c[8][4];
#pragma unroll
            for (int n = 0; n < 8; n++)
#pragma unroll
                for (int j = 0; j < 4; j++) c[n][j] = 0.f;

#pragma unroll
            for (int kb = 0; kb < 8; kb++) {
                const uint32_t* kp = sKb + lr * HKS + kb * 8 + 2 * lc;
#pragma unroll
                for (int nf = 0; nf < 8; nf++) {
                    uint2 kv = *(const uint2*)(kp + nf * 8 * HKS);
                    uint32_t b[2] = {kv.x, kv.y};
                    mma16(c[nf], qf[kb], b);
                }
            }

            if (t * 64 + 63 > qt * 128 + m_off) {
#pragma unroll
                for (int nf = 0; nf < 8; nf++) {
#pragma unroll
                    for (int j = 0; j < 4; j++) {
                        int col = t * 64 + nf * 8 + 2 * lc + (j & 1);
                        int row = qt * 128 + m_off + lr + 8 * (j >> 1);
                        if (col > row) c[nf][j] = -1e30f;
                    }
                }
            }

            float mt0 = -1e30f, mt1 = -1e30f;
#pragma unroll
            for (int nf = 0; nf < 8; nf++) {
                mt0 = fmaxf(mt0, fmaxf(c[nf][0], c[nf][1]));
                mt1 = fmaxf(mt1, fmaxf(c[nf][2], c[nf][3]));
            }
#pragma unroll
            for (int d = 1; d <= 2; d <<= 1) {
                mt0 = fmaxf(mt0, __shfl_xor_sync(0xffffffffu, mt0, d));
                mt1 = fmaxf(mt1, __shfl_xor_sync(0xffffffffu, mt1, d));
            }
            float nm0 = fmaxf(m0, mt0), nm1 = fmaxf(m1, mt1);
            float corr0 = __expf(m0 - nm0), corr1 = __expf(m1 - nm1);
            m0 = nm0; m1 = nm1;

            float s0 = 0.f, s1 = 0.f;
#pragma unroll
            for (int nf = 0; nf < 8; nf++) {
                c[nf][0] = __expf(c[nf][0] - nm0); s0 += c[nf][0];
                c[nf][1] = __expf(c[nf][1] - nm0); s0 += c[nf][1];
                c[nf][2] = __expf(c[nf][2] - nm1); s1 += c[nf][2];
                c[nf][3] = __expf(c[nf][3] - nm1); s1 += c[nf][3];
            }
#pragma unroll
            for (int d = 1; d <= 2; d <<= 1) {
                s0 += __shfl_xor_sync(0xffffffffu, s0, d);
                s1 += __shfl_xor_sync(0xffffffffu, s1, d);
            }
            l0 = l0 * corr0 + s0;
            l1 = l1 * corr1 + s1;

            if (__any_sync(0xffffffffu, (corr0 != 1.f) || (corr1 != 1.f))) {
#pragma unroll
                for (int n = 0; n < 16; n++) {
                    o[n][0] *= corr0; o[n][1] *= corr0;
                    o[n][2] *= corr1; o[n][3] *= corr1;
                }
            }

#pragma unroll
            for (int kp2 = 0; kp2 < 4; kp2++) {
                uint32_t a[4];
                a[0] = f2h2(c[2 * kp2][0],     c[2 * kp2][1]);
                a[1] = f2h2(c[2 * kp2][2],     c[2 * kp2][3]);
                a[2] = f2h2(c[2 * kp2 + 1][0], c[2 * kp2 + 1][1]);
                a[3] = f2h2(c[2 * kp2 + 1][2], c[2 * kp2 + 1][3]);
                const uint32_t* vp = sVb + lr * HVS + kp2 * 8 + 2 * lc;
#pragma unroll
                for (int nf = 0; nf < 16; nf++) {
                    uint2 vv = *(const uint2*)(vp + nf * 8 * HVS);
                    uint32_t b[2] = {vv.x, vv.y};
                    mma16(o[nf], a, b);
                }
            }
        }
        __syncthreads();
    }

    const float inv0 = 1.0f / l0;
    const float inv1 = 1.0f / l1;
    const int b = bh / Hh;
    const int h = bh % Hh;
    const size_t mrow0 = (size_t)b * 2048 + qt * 128 + m_off + lr;
    const size_t mrow1 = mrow0 + 8;
#pragma unroll
    for (int nf = 0; nf < 16; nf++) {
        int j = h * 64 + nf * 4 + lc;
        size_t slot = (size_t)(j >> 3) * 8 + ppos(j & 7);
        AP[mrow0 * 1024 + slot] = f2h2(o[nf][0] * inv0, o[nf][1] * inv0);
        AP[mrow1 * 1024 + slot] = f2h2(o[nf][2] * inv1, o[nf][3] * inv1);
    }
}

// ---------------------------------------------------------------------------

extern "C" void kernel_launch(void* const* d_in, const int* in_sizes, int n_in,
                              void* d_out, int out_size)
{
    const float* x  = (const float*)d_in[0];
    const float* Wq = (const float*)d_in[1];
    const float* bq = (const float*)d_in[2];
    const float* Wk = (const float*)d_in[3];
    const float* bk = (const float*)d_in[4];
    const float* Wv = (const float*)d_in[5];
    const float* bv = (const float*)d_in[6];
    const float* Wd = (const float*)d_in[7];
    const float* bd = (const float*)d_in[8];

    float* out = (float*)d_out;
    float* a_out = out;
    float* k_out = out + (size_t)Bb * Ss * Dd;
    float* v_out = k_out + (size_t)Bb * Ss * Dd;

    uint32_t *xp, *wpq, *wpk, *wpv, *wpd, *qp, *kp, *vp, *ap;
    cudaGetSymbolAddress((void**)&xp,  g_XPh);
    cudaGetSymbolAddress((void**)&wpq, g_WPq);
    cudaGetSymbolAddress((void**)&wpk, g_WPk);
    cudaGetSymbolAddress((void**)&wpv, g_WPv);
    cudaGetSymbolAddress((void**)&wpd, g_WPd);
    cudaGetSymbolAddress((void**)&qp,  g_QPh);
    cudaGetSymbolAddress((void**)&kp,  g_KPh);
    cudaGetSymbolAddress((void**)&vp,  g_VPh);
    cudaGetSymbolAddress((void**)&ap,  g_APh);

    xprep_h<<<Mtot, 256>>>(x, xp);
    wprep4_h<<<dim3(8, 128, 4), 256>>>(Wq, Wk, Wv, Wd, wpq, wpk, wpv, wpd);

    size_t gsm = 2 * (size_t)HGBUF * sizeof(uint32_t);
    cudaFuncSetAttribute(gemm_h, cudaFuncAttributeMaxDynamicSharedMemorySize, (int)gsm);

    const int PERSIST = 296;   // 2 CTAs/SM x 148 SMs

    // fused QKV (persistent): tiles 0..1535, z = tile>>9; modes 1,2,3
    gemm_h<<<PERSIST, 256, gsm>>>(
        xp, wpq, wpk, wpv, bq, bk, bv,
        nullptr, k_out, v_out, qp, kp, vp, 1, 1536);

    size_t asm_ = (size_t)(HSQ + 2 * HSK + 2 * HSV) * sizeof(uint32_t);
    cudaFuncSetAttribute(attn_h, cudaFuncAttributeMaxDynamicSharedMemorySize, (int)asm_);
    attn_h<<<dim3(Ss / 128, Bb * Hh), 256, asm_>>>(qp, kp, vp, ap);

    // final projection (persistent): tiles 0..511, mode 0
    gemm_h<<<PERSIST, 256, gsm>>>(
        ap, wpd, wpd, wpd, bd, bd, bd,
        a_out, a_out, a_out, nullptr, nullptr, nullptr, 0, 512);
}

// round 15
// speedup vs baseline: 2.1252x; 1.0563x over previous
#include <cuda_runtime.h>
#include <cuda_fp16.h>
#include <cstdint>

#define Bb 2
#define Ss 2048
#define Dd 2048
#define Hh 16
#define HD 128
#define Mtot (Bb*Ss)

// fp16 pair-layout scratch (half2 stored as uint32_t).
// Row of K halfs -> K/2 half2, grouped in 16-k blocks (8 half2); within a
// block, half2 j (local 0..7) at position pos(j) = (j&3)*2 + (j>>2). A thread
// (lc) reads positions {2lc,2lc+1} as one LDS.64 = m16n8k16 klo/khi pair.
// XPh/APh: [Mtot][1024]
// WPh:     [128 kb][2048 n][8]
// QPh/KPh: [bh=32][s=2048][64]
// VPh:     [bh=32][128 d][1024]  (pairs along s)
__device__ uint32_t g_XPh[(size_t)Mtot * 1024];
__device__ uint32_t g_WPq[(size_t)128 * 2048 * 8];
__device__ uint32_t g_WPk[(size_t)128 * 2048 * 8];
__device__ uint32_t g_WPv[(size_t)128 * 2048 * 8];
__device__ uint32_t g_WPd[(size_t)128 * 2048 * 8];
__device__ uint32_t g_QPh[(size_t)Bb * Hh * Ss * 64];
__device__ uint32_t g_KPh[(size_t)Bb * Hh * Ss * 64];
__device__ uint32_t g_VPh[(size_t)Bb * Hh * 128 * 1024];
__device__ uint32_t g_APh[(size_t)Mtot * 1024];

__device__ __forceinline__ uint32_t f2h2(float a, float b) {
    __half2 h = __floats2half2_rn(a, b);
    return *(uint32_t*)&h;
}

__device__ __forceinline__ void mma16(float* c, const uint32_t* a, const uint32_t* b) {
    asm volatile(
        "mma.sync.aligned.m16n8k16.row.col.f32.f16.f16.f32 "
        "{%0,%1,%2,%3}, {%4,%5,%6,%7}, {%8,%9}, {%0,%1,%2,%3};"
        : "+f"(c[0]), "+f"(c[1]), "+f"(c[2]), "+f"(c[3])
        : "r"(a[0]), "r"(a[1]), "r"(a[2]), "r"(a[3]), "r"(b[0]), "r"(b[1]));
}
__device__ __forceinline__ void cpa16(void* dst, const void* src) {
    uint32_t d = (uint32_t)__cvta_generic_to_shared(dst);
    asm volatile("cp.async.cg.shared.global [%0], [%1], 16;" :: "r"(d), "l"(src));
}
#define CP_COMMIT asm volatile("cp.async.commit_group;")
#define CP_WAIT1  asm volatile("cp.async.wait_group 1;")
#define CP_WAIT0  asm volatile("cp.async.wait_group 0;")

__device__ __forceinline__ int ppos(int jl) { return (jl & 3) * 2 + ((jl >> 2) & 1); }

// ---------------------------------------------------------------------------
// Prep kernels (R12, verified)
// ---------------------------------------------------------------------------
__global__ void xprep_h(const float* __restrict__ X, uint32_t* __restrict__ XP) {
    __shared__ float s[2048];
    const int m = blockIdx.x;
    const int tid = threadIdx.x;
    const float* src = X + (size_t)m * 2048;
#pragma unroll
    for (int i = 0; i < 2; i++) {
        int f = i * 256 + tid;
        *(float4*)(s + f * 4) = *(const float4*)(src + f * 4);
    }
    __syncthreads();
    const int b = tid >> 1;
    const int w0 = (tid & 1) * 4;
    uint32_t o[4];
#pragma unroll
    for (int q = 0; q < 4; q++) {
        int w = w0 + q;
        int j = b * 8 + (w >> 1) + (w & 1) * 4;
        o[q] = f2h2(s[2 * j], s[2 * j + 1]);
    }
    *(uint4*)(XP + (size_t)m * 1024 + tid * 4) = make_uint4(o[0], o[1], o[2], o[3]);
}

__global__ void wprep4_h(const float* __restrict__ W0, const float* __restrict__ W1,
                         const float* __restrict__ W2, const float* __restrict__ W3,
                         uint32_t* __restrict__ P0, uint32_t* __restrict__ P1,
                         uint32_t* __restrict__ P2, uint32_t* __restrict__ P3) {
    __shared__ float s[16 * 260];
    const int n0 = blockIdx.x * 256;
    const int kb = blockIdx.y;
    const int z  = blockIdx.z;
    const int tid = threadIdx.x;
    const float* W = (z == 0) ? W0 : (z == 1) ? W1 : (z == 2) ? W2 : W3;
    uint32_t* WP   = (z == 0) ? P0 : (z == 1) ? P1 : (z == 2) ? P2 : P3;
#pragma unroll
    for (int i = 0; i < 4; i++) {
        int f = i * 256 + tid;
        int r = f >> 6, c4 = (f & 63) * 4;
        float4 v = *(const float4*)(W + (size_t)(kb * 16 + r) * 2048 + n0 + c4);
        *(float4*)(s + r * 260 + c4) = v;
    }
    __syncthreads();
    const int n = tid;
    uint32_t o[8];
#pragma unroll
    for (int w = 0; w < 8; w++) {
        int j = (w >> 1) + (w & 1) * 4;
        o[w] = f2h2(s[(2 * j) * 260 + n], s[(2 * j + 1) * 260 + n]);
    }
    uint32_t* dst = WP + ((size_t)kb * 2048 + n0 + n) * 8;
    *(uint4*)(dst)     = make_uint4(o[0], o[1], o[2], o[3]);
    *(uint4*)(dst + 4) = make_uint4(o[4], o[5], o[6], o[7]);
}

// ---------------------------------------------------------------------------
// PERSISTENT fp16 tensor-core GEMM (R13, verified). Grid = 296 CTAs.
// Tile map: bx = t&15 (N), by = (t>>4)&31 (M), z = t>>9 (weight set).
// modes: 0 plain fp32 C; 1 Q->QPh (qscale); 2 K->k_out+KPh; 3 V->v_out+VPh
// ---------------------------------------------------------------------------
#define HASTR 24
#define HABUF (128 * HASTR)
#define HBBUF (2 * 128 * 8)
#define HGBUF (HABUF + HBBUF)

__global__ __launch_bounds__(256, 2)
void gemm_h(const uint32_t* __restrict__ Ap,
            const uint32_t* __restrict__ Wa, const uint32_t* __restrict__ Wb,
            const uint32_t* __restrict__ Wc,
            const float* __restrict__ ba, const float* __restrict__ bb,
            const float* __restrict__ bc,
            float* __restrict__ ra, float* __restrict__ rb, float* __restrict__ rc,
            uint32_t* __restrict__ pa, uint32_t* __restrict__ pb, uint32_t* __restrict__ pc,
            int modebase, int ntiles)
{
    extern __shared__ uint32_t smu[];

    const int tid  = threadIdx.x;
    const int lane = tid & 31;
    const int wid  = tid >> 5;
    const int mb   = (wid >> 1) * 32;
    const int nb   = (wid & 1) * 64;
    const int lr   = lane >> 2;
    const int lc   = lane & 3;

    for (int tile = blockIdx.x; tile < ntiles; tile += gridDim.x) {
        const int bx = tile & 15;
        const int by = (tile >> 4) & 31;
        const int z  = tile >> 9;
        const uint32_t* WP = (z == 0) ? Wa : (z == 1) ? Wb : Wc;
        const float* bias  = (z == 0) ? ba : (z == 1) ? bb : bc;
        float* Craw        = (z == 0) ? ra : (z == 1) ? rb : rc;
        uint32_t* Cpair    = (z == 0) ? pa : (z == 1) ? pb : pc;
        const int mode = modebase ? (1 + z) : 0;

        float acc[2][8][4];
#pragma unroll
        for (int f = 0; f < 2; f++)
#pragma unroll
            for (int g = 0; g < 8; g++)
#pragma unroll
                for (int t = 0; t < 4; t++) acc[f][g][t] = 0.f;

        auto issue = [&](int kt, int buf) {
            uint32_t* As = smu + buf * HGBUF;
            uint32_t* Bs = As + HABUF;
#pragma unroll
            for (int j = 0; j < 2; j++) {
                int idx = j * 256 + tid;
                int m = idx >> 2, ch = idx & 3;
                cpa16(As + m * HASTR + ch * 4,
                      Ap + (size_t)(by * 128 + m) * 1024 + kt * 16 + ch * 4);
            }
#pragma unroll
            for (int j = 0; j < 2; j++) {
                int idx = j * 256 + tid;
                int kb = idx >> 8, r = idx & 255, n = r >> 1, ch = r & 1;
                cpa16(Bs + kb * 1024 + n * 8 + ch * 4,
                      WP + ((size_t)(kt * 2 + kb) * 2048 + bx * 128 + n) * 8 + ch * 4);
            }
        };

        issue(0, 0);
        CP_COMMIT;

        for (int kt = 0; kt < 64; kt++) {
            CP_WAIT0;
            __syncthreads();
            if (kt < 63) { issue(kt + 1, (kt + 1) & 1); CP_COMMIT; }

            const uint32_t* As = smu + (kt & 1) * HGBUF;
            const uint32_t* Bs = As + HABUF;

#pragma unroll
            for (int kb = 0; kb < 2; kb++) {
                const int ao = kb * 8 + 2 * lc;
                uint2 x0 = *(const uint2*)(As + (mb + lr) * HASTR + ao);
                uint2 x1 = *(const uint2*)(As + (mb + lr + 8) * HASTR + ao);
                uint2 x2 = *(const uint2*)(As + (mb + 16 + lr) * HASTR + ao);
                uint2 x3 = *(const uint2*)(As + (mb + 24 + lr) * HASTR + ao);
                uint32_t a0[4] = {x0.x, x1.x, x0.y, x1.y};
                uint32_t a1[4] = {x2.x, x3.x, x2.y, x3.y};
                const uint32_t* bp = Bs + kb * 1024 + (nb + lr) * 8 + 2 * lc;
#pragma unroll
                for (int g = 0; g < 8; g++) {
                    uint2 bv = *(const uint2*)(bp + g * 64);
                    uint32_t b[2] = {bv.x, bv.y};
                    mma16(acc[0][g], a0, b);
                    mma16(acc[1][g], a1, b);
                }
            }
            __syncthreads();
        }

        const float qscale = 0.08838834764831845f;
#pragma unroll
        for (int f = 0; f < 2; f++) {
#pragma unroll
            for (int g = 0; g < 8; g++) {
#pragma unroll
                for (int ii = 0; ii < 2; ii++) {
                    int row = by * 128 + mb + f * 16 + lr + 8 * ii;
                    int col0 = bx * 128 + nb + g * 8 + lc * 2;
                    float v0 = acc[f][g][ii * 2 + 0] + bias[col0];
                    float v1 = acc[f][g][ii * 2 + 1] + bias[col0 + 1];
                    if (mode == 0) {
                        float* p = Craw + (size_t)row * Dd + col0;
                        p[0] = v0; p[1] = v1;
                    } else {
                        int b_ = row >> 11, s_ = row & 2047;
                        int h_ = col0 >> 7, d_ = col0 & 127;
                        size_t bh = (size_t)(b_ * Hh + h_);
                        if (mode >= 2) {
                            float* p = Craw + (bh * Ss + s_) * HD + d_;
                            p[0] = v0; p[1] = v1;
                        }
                        if (mode == 3) {
                            float u0 = __shfl_xor_sync(0xffffffffu, v0, 4);
                            float u1 = __shfl_xor_sync(0xffffffffu, v1, 4);
                            if (!(lr & 1)) {
                                int js = s_ >> 1;
                                size_t slot = (size_t)(js >> 3) * 8 + ppos(js & 7);
                                Cpair[(bh * 128 + d_) * 1024 + slot]     = f2h2(v0, u0);
                                Cpair[(bh * 128 + d_ + 1) * 1024 + slot] = f2h2(v1, u1);
                            }
                        } else {
                            float s0 = (mode == 1) ? v0 * qscale : v0;
                            float s1 = (mode == 1) ? v1 * qscale : v1;
                            int j = d_ >> 1;
                            Cpair[(bh * Ss + s_) * 64 + (j >> 3) * 8 + ppos(j & 7)] = f2h2(s0, s1);
                        }
                    }
                }
            }
        }
    }
}

// ---------------------------------------------------------------------------
// fp16 flash attention, 128-thread CTAs (Q-tile 64, 4 warps x 16 rows),
// 2 CTAs/SM. Per-warp math identical to R12/R13. KV tiles 64, double-buffered.
// sQ [64][72], sK 2x[64][72], sV 2x[128][40]  (u32) = 94 KB/CTA.
// ---------------------------------------------------------------------------
#define HQS 72
#define HKS 72
#define HVS 40
#define ASQ (64 * HQS)
#define ASK (64 * HKS)
#define ASV (128 * HVS)

__global__ __launch_bounds__(128, 2)
void attn_h(const uint32_t* __restrict__ QP, const uint32_t* __restrict__ KP,
            const uint32_t* __restrict__ VP, uint32_t* __restrict__ AP)
{
    extern __shared__ uint32_t smu[];
    uint32_t* sQ = smu;                  // ASQ
    uint32_t* sK = sQ + ASQ;             // 2*ASK
    uint32_t* sV = sK + 2 * ASK;         // 2*ASV

    const int qt  = (gridDim.x - 1) - blockIdx.x;   // 31..0, big first
    const int bh  = blockIdx.y;
    const int tid = threadIdx.x;
    const int lane = tid & 31;
    const int wid  = tid >> 5;           // 0..3
    const int lr   = lane >> 2;
    const int lc   = lane & 3;
    const int m_off = wid * 16;

    const uint32_t* Qg = QP + ((size_t)bh * Ss + (size_t)qt * 64) * 64;
    const uint32_t* Kg = KP + (size_t)bh * Ss * 64;
    const uint32_t* Vg = VP + (size_t)bh * 128 * 1024;

    // group 0: Q (64 rows x 16 chunks)
#pragma unroll
    for (int i = 0; i < 8; i++) {
        int idx = i * 128 + tid;
        int row = idx >> 4, ch = idx & 15;
        cpa16(sQ + row * HQS + ch * 4, Qg + (size_t)row * 64 + ch * 4);
    }
    CP_COMMIT;
    // group 1: KV tile 0
#pragma unroll
    for (int i = 0; i < 8; i++) {
        int idx = i * 128 + tid;
        int row = idx >> 4, ch = idx & 15;
        cpa16(sK + row * HKS + ch * 4, Kg + (size_t)row * 64 + ch * 4);
    }
#pragma unroll
    for (int i = 0; i < 8; i++) {
        int idx = i * 128 + tid;
        int d = idx >> 3, ch = idx & 7;
        cpa16(sV + d * HVS + ch * 4, Vg + (size_t)d * 1024 + ch * 4);
    }
    CP_COMMIT;

    CP_WAIT1;
    __syncthreads();
    uint32_t qf[8][4];
#pragma unroll
    for (int kb = 0; kb < 8; kb++) {
        uint2 q0 = *(const uint2*)(sQ + (m_off + lr) * HQS + kb * 8 + 2 * lc);
        uint2 q1 = *(const uint2*)(sQ + (m_off + lr + 8) * HQS + kb * 8 + 2 * lc);
        qf[kb][0] = q0.x; qf[kb][1] = q1.x; qf[kb][2] = q0.y; qf[kb][3] = q1.y;
    }

    float o[16][4];
#pragma unroll
    for (int n = 0; n < 16; n++)
#pragma unroll
        for (int j = 0; j < 4; j++) o[n][j] = 0.f;
    float m0 = -1e30f, m1 = -1e30f, l0 = 0.f, l1 = 0.f;

    const int tmax = qt;                 // KV tiles 0..qt cover the causal span

    for (int t = 0; t <= tmax; t++) {
        const int buf = t & 1;
        if (t < tmax) {
            const int nb2 = (t + 1) & 1;
            uint32_t* dK = sK + nb2 * ASK;
            uint32_t* dV = sV + nb2 * ASV;
            const uint32_t* gK = Kg + (size_t)(t + 1) * 64 * 64;
            const uint32_t* gV = Vg + (size_t)(t + 1) * 32;
#pragma unroll
            for (int i = 0; i < 8; i++) {
                int idx = i * 128 + tid;
                int row = idx >> 4, ch = idx & 15;
                cpa16(dK + row * HKS + ch * 4, gK + (size_t)row * 64 + ch * 4);
            }
#pragma unroll
            for (int i = 0; i < 8; i++) {
                int idx = i * 128 + tid;
                int d = idx >> 3, ch = idx & 7;
                cpa16(dV + d * HVS + ch * 4, gV + (size_t)d * 1024 + ch * 4);
            }
            CP_COMMIT;
            CP_WAIT1;
        } else {
            CP_WAIT0;
        }
        __syncthreads();

        {
            const uint32_t* sKb = sK + buf * ASK;
            const uint32_t* sVb = sV + buf * ASV;

            // ---- S = Q @ K^T ----
            float c[8][4];
#pragma unroll
            for (int n = 0; n < 8; n++)
#pragma unroll
                for (int j = 0; j < 4; j++) c[n][j] = 0.f;

#pragma unroll
            for (int kb = 0; kb < 8; kb++) {
                const uint32_t* kp = sKb + lr * HKS + kb * 8 + 2 * lc;
#pragma unroll
                for (int nf = 0; nf < 8; nf++) {
                    uint2 kv = *(const uint2*)(kp + nf * 8 * HKS);
                    uint32_t b[2] = {kv.x, kv.y};
                    mma16(c[nf], qf[kb], b);
                }
            }

            // ---- causal mask (only diagonal tile t == qt) ----
            if (t * 64 + 63 > qt * 64 + m_off) {
#pragma unroll
                for (int nf = 0; nf < 8; nf++) {
#pragma unroll
                    for (int j = 0; j < 4; j++) {
                        int col = t * 64 + nf * 8 + 2 * lc + (j & 1);
                        int row = qt * 64 + m_off + lr + 8 * (j >> 1);
                        if (col > row) c[nf][j] = -1e30f;
                    }
                }
            }

            // ---- online softmax (rows lr, lr+8) ----
            float mt0 = -1e30f, mt1 = -1e30f;
#pragma unroll
            for (int nf = 0; nf < 8; nf++) {
                mt0 = fmaxf(mt0, fmaxf(c[nf][0], c[nf][1]));
                mt1 = fmaxf(mt1, fmaxf(c[nf][2], c[nf][3]));
            }
#pragma unroll
            for (int d = 1; d <= 2; d <<= 1) {
                mt0 = fmaxf(mt0, __shfl_xor_sync(0xffffffffu, mt0, d));
                mt1 = fmaxf(mt1, __shfl_xor_sync(0xffffffffu, mt1, d));
            }
            float nm0 = fmaxf(m0, mt0), nm1 = fmaxf(m1, mt1);
            float corr0 = __expf(m0 - nm0), corr1 = __expf(m1 - nm1);
            m0 = nm0; m1 = nm1;

            float s0 = 0.f, s1 = 0.f;
#pragma unroll
            for (int nf = 0; nf < 8; nf++) {
                c[nf][0] = __expf(c[nf][0] - nm0); s0 += c[nf][0];
                c[nf][1] = __expf(c[nf][1] - nm0); s0 += c[nf][1];
                c[nf][2] = __expf(c[nf][2] - nm1); s1 += c[nf][2];
                c[nf][3] = __expf(c[nf][3] - nm1); s1 += c[nf][3];
            }
#pragma unroll
            for (int d = 1; d <= 2; d <<= 1) {
                s0 += __shfl_xor_sync(0xffffffffu, s0, d);
                s1 += __shfl_xor_sync(0xffffffffu, s1, d);
            }
            l0 = l0 * corr0 + s0;
            l1 = l1 * corr1 + s1;

            if (__any_sync(0xffffffffu, (corr0 != 1.f) || (corr1 != 1.f))) {
#pragma unroll
                for (int n = 0; n < 16; n++) {
                    o[n][0] *= corr0; o[n][1] *= corr0;
                    o[n][2] *= corr1; o[n][3] *= corr1;
                }
            }

            // ---- O += P @ V  (C-frag layout == A-frag layout: no shfl) ----
#pragma unroll
            for (int kp2 = 0; kp2 < 4; kp2++) {
                uint32_t a[4];
                a[0] = f2h2(c[2 * kp2][0],     c[2 * kp2][1]);
                a[1] = f2h2(c[2 * kp2][2],     c[2 * kp2][3]);
                a[2] = f2h2(c[2 * kp2 + 1][0], c[2 * kp2 + 1][1]);
                a[3] = f2h2(c[2 * kp2 + 1][2], c[2 * kp2 + 1][3]);
                const uint32_t* vp = sVb + lr * HVS + kp2 * 8 + 2 * lc;
#pragma unroll
                for (int nf = 0; nf < 16; nf++) {
                    uint2 vv = *(const uint2*)(vp + nf * 8 * HVS);
                    uint32_t b[2] = {vv.x, vv.y};
                    mma16(o[nf], a, b);
                }
            }
        }
        __syncthreads();
    }

    // ---- epilogue: normalize, write APh (pair layout for final GEMM) ----
    const float inv0 = 1.0f / l0;
    const float inv1 = 1.0f / l1;
    const int b = bh / Hh;
    const int h = bh % Hh;
    const size_t mrow0 = (size_t)b * 2048 + qt * 64 + m_off + lr;
    const size_t mrow1 = mrow0 + 8;
#pragma unroll
    for (int nf = 0; nf < 16; nf++) {
        int j = h * 64 + nf * 4 + lc;
        size_t slot = (size_t)(j >> 3) * 8 + ppos(j & 7);
        AP[mrow0 * 1024 + slot] = f2h2(o[nf][0] * inv0, o[nf][1] * inv0);
        AP[mrow1 * 1024 + slot] = f2h2(o[nf][2] * inv1, o[nf][3] * inv1);
    }
}

// ---------------------------------------------------------------------------

extern "C" void kernel_launch(void* const* d_in, const int* in_sizes, int n_in,
                              void* d_out, int out_size)
{
    const float* x  = (const float*)d_in[0];
    const float* Wq = (const float*)d_in[1];
    const float* bq = (const float*)d_in[2];
    const float* Wk = (const float*)d_in[3];
    const float* bk = (const float*)d_in[4];
    const float* Wv = (const float*)d_in[5];
    const float* bv = (const float*)d_in[6];
    const float* Wd = (const float*)d_in[7];
    const float* bd = (const float*)d_in[8];

    float* out = (float*)d_out;
    float* a_out = out;
    float* k_out = out + (size_t)Bb * Ss * Dd;
    float* v_out = k_out + (size_t)Bb * Ss * Dd;

    uint32_t *xp, *wpq, *wpk, *wpv, *wpd, *qp, *kp, *vp, *ap;
    cudaGetSymbolAddress((void**)&xp,  g_XPh);
    cudaGetSymbolAddress((void**)&wpq, g_WPq);
    cudaGetSymbolAddress((void**)&wpk, g_WPk);
    cudaGetSymbolAddress((void**)&wpv, g_WPv);
    cudaGetSymbolAddress((void**)&wpd, g_WPd);
    cudaGetSymbolAddress((void**)&qp,  g_QPh);
    cudaGetSymbolAddress((void**)&kp,  g_KPh);
    cudaGetSymbolAddress((void**)&vp,  g_VPh);
    cudaGetSymbolAddress((void**)&ap,  g_APh);

    xprep_h<<<Mtot, 256>>>(x, xp);
    wprep4_h<<<dim3(8, 128, 4), 256>>>(Wq, Wk, Wv, Wd, wpq, wpk, wpv, wpd);

    size_t gsm = 2 * (size_t)HGBUF * sizeof(uint32_t);
    cudaFuncSetAttribute(gemm_h, cudaFuncAttributeMaxDynamicSharedMemorySize, (int)gsm);

    const int PERSIST = 296;   // 2 CTAs/SM x 148 SMs

    // fused QKV (persistent): tiles 0..1535, z = tile>>9; modes 1,2,3
    gemm_h<<<PERSIST, 256, gsm>>>(
        xp, wpq, wpk, wpv, bq, bk, bv,
        nullptr, k_out, v_out, qp, kp, vp, 1, 1536);

    size_t asm_ = (size_t)(ASQ + 2 * ASK + 2 * ASV) * sizeof(uint32_t);
    cudaFuncSetAttribute(attn_h, cudaFuncAttributeMaxDynamicSharedMemorySize, (int)asm_);
    attn_h<<<dim3(Ss / 64, Bb * Hh), 128, asm_>>>(qp, kp, vp, ap);

    // final projection (persistent): tiles 0..511, mode 0
    gemm_h<<<PERSIST, 256, gsm>>>(
        ap, wpd, wpd, wpd, bd, bd, bd,
        a_out, a_out, a_out, nullptr, nullptr, nullptr, 0, 512);
}